// round 4
// baseline (speedup 1.0000x reference)
#include <cuda_runtime.h>
#include <cuda_bf16.h>
#include <cstdint>

#define NN 100000
#define NE 640000
#define INC 256
#define HID 128
#define NB  ((NN + 1023) / 1024)

// Scratch (__device__ globals — allocation-free rule)
__device__ float g_h[(size_t)NN * HID];
__device__ float g_p[(size_t)NN * HID];
__device__ float g_dinv[NN];
__device__ int   g_cnt[NN];
__device__ int   g_off[NN + 1];
__device__ int   g_cursor[NN];
__device__ int   g_es[NE];
__device__ float g_en[NE];
__device__ int   g_bsum[128];

// ---------------------------------------------------------------------------
// CSR construction
// ---------------------------------------------------------------------------
__global__ void k_cnt_zero() {
    int n = blockIdx.x * blockDim.x + threadIdx.x;
    if (n < NN) g_cnt[n] = 0;
}
__global__ void k_count(const int* __restrict__ dst) {
    int e = blockIdx.x * blockDim.x + threadIdx.x;
    if (e < NE) atomicAdd(&g_cnt[dst[e]], 1);
}
__global__ void k_dinv() {
    int n = blockIdx.x * blockDim.x + threadIdx.x;
    if (n < NN) g_dinv[n] = rsqrtf(1.0f + (float)g_cnt[n]);
}
__global__ __launch_bounds__(1024) void k_blocksum() {
    __shared__ int sm[1024];
    int i = blockIdx.x * 1024 + threadIdx.x;
    int v = (i < NN) ? g_cnt[i] : 0;
    sm[threadIdx.x] = v;
    __syncthreads();
#pragma unroll
    for (int d = 512; d > 0; d >>= 1) {
        if (threadIdx.x < d) sm[threadIdx.x] += sm[threadIdx.x + d];
        __syncthreads();
    }
    if (threadIdx.x == 0) g_bsum[blockIdx.x] = sm[0];
}
__global__ void k_bscan() {
    __shared__ int sm[128];
    int t = threadIdx.x;
    int v = (t < NB) ? g_bsum[t] : 0;
    sm[t] = v;
    __syncthreads();
#pragma unroll
    for (int d = 1; d < 128; d <<= 1) {
        int x = (t >= d) ? sm[t - d] : 0;
        __syncthreads();
        sm[t] += x;
        __syncthreads();
    }
    if (t < 128) g_bsum[t] = sm[t] - v;
}
__global__ __launch_bounds__(1024) void k_offsets() {
    __shared__ int sm[1024];
    int i = blockIdx.x * 1024 + threadIdx.x;
    int v = (i < NN) ? g_cnt[i] : 0;
    sm[threadIdx.x] = v;
    __syncthreads();
#pragma unroll
    for (int d = 1; d < 1024; d <<= 1) {
        int x = (threadIdx.x >= d) ? sm[threadIdx.x - d] : 0;
        __syncthreads();
        sm[threadIdx.x] += x;
        __syncthreads();
    }
    if (i < NN) {
        int off = g_bsum[blockIdx.x] + sm[threadIdx.x] - v;
        g_off[i] = off;
        g_cursor[i] = off;
    }
    if (i == 0) g_off[NN] = NE;
}
__global__ void k_scatter(const int* __restrict__ src, const int* __restrict__ dst) {
    int e = blockIdx.x * blockDim.x + threadIdx.x;
    if (e >= NE) return;
    int s = src[e], d = dst[e];
    int pos = atomicAdd(&g_cursor[d], 1);
    g_es[pos] = s;
    g_en[pos] = g_dinv[s] * g_dinv[d];
}

// ---------------------------------------------------------------------------
// Tensor-core GEMM: C[M,128] = op(A[M,KT]) @ B[KT,128], fp32 in/out.
// bf16 split (hi+lo), 3 mma passes, fp32 accumulate.
// Block: 256 thr (8 warps, 4M x 2N). Block tile 128x128, warp tile 32x64.
// ---------------------------------------------------------------------------
#define MMA_BF16(c0,c1,c2,c3,a0,a1,a2,a3,b0,b1)                                  \
    asm volatile("mma.sync.aligned.m16n8k16.row.col.f32.bf16.bf16.f32 "          \
        "{%0,%1,%2,%3}, {%4,%5,%6,%7}, {%8,%9}, {%0,%1,%2,%3};"                  \
        : "+f"(c0), "+f"(c1), "+f"(c2), "+f"(c3)                                  \
        : "r"(a0), "r"(a1), "r"(a2), "r"(a3), "r"(b0), "r"(b1))

__device__ __forceinline__ void split_bf16(float x, unsigned short& hi, unsigned short& lo) {
    __nv_bfloat16 h = __float2bfloat16(x);
    float hf = __bfloat162float(h);
    __nv_bfloat16 l = __float2bfloat16(x - hf);
    hi = *reinterpret_cast<unsigned short*>(&h);
    lo = *reinterpret_cast<unsigned short*>(&l);
}

#define LDA 40  // padded leading dim (uint16) for conflict-free frag loads

template <int KT, bool RELU>
__global__ __launch_bounds__(256, 2) void tgemm128(
    const float* __restrict__ A,
    const float* __restrict__ B0, const float* __restrict__ B1, int ldb,
    float* __restrict__ C, int M)
{
    __shared__ unsigned short As_hi[128][LDA];
    __shared__ unsigned short As_lo[128][LDA];
    __shared__ unsigned short Bs_hi[128][LDA];  // [n][k]
    __shared__ unsigned short Bs_lo[128][LDA];

    const int t = threadIdx.x;
    const int w = t >> 5;
    const int lane = t & 31;
    const int g = lane >> 2;     // group id
    const int tg = lane & 3;     // thread-in-group
    const int warp_m = (w & 3) * 32;
    const int warp_n = (w >> 2) * 64;
    const int blockRow = blockIdx.x * 128;

    // A tile load mapping: thread loads row t>>1, k cols (t&1)*16 .. +15
    const int ar = t >> 1;
    const int ak = (t & 1) * 16;
    const int grow = blockRow + ar;
    const bool arow_ok = (grow < M);
    const float* aptr = A + (size_t)grow * KT + ak;

    // B tile load mapping: thread loads k row t>>3, n cols (t&7)*16 .. +15
    const int bkl = t >> 3;
    const int bnb = (t & 7) * 16;
    const float* bptr = (bnb < 64) ? (B0 + bnb) : (B1 + (bnb - 64));

    float acc[2][8][4];
#pragma unroll
    for (int i = 0; i < 2; i++)
#pragma unroll
        for (int j = 0; j < 8; j++)
#pragma unroll
            for (int k = 0; k < 4; k++) acc[i][j][k] = 0.0f;

#pragma unroll 1
    for (int kt = 0; kt < KT; kt += 32) {
        __syncthreads();  // protect tiles from previous iteration

        // ---- load & convert A chunk: rows 0..127, k kt..kt+31 ----
        {
#pragma unroll
            for (int q = 0; q < 4; q++) {
                float4 v = make_float4(0.f, 0.f, 0.f, 0.f);
                if (arow_ok) v = *(const float4*)(aptr + kt + q * 4);
                if (RELU) {
                    v.x = fmaxf(v.x, 0.f); v.y = fmaxf(v.y, 0.f);
                    v.z = fmaxf(v.z, 0.f); v.w = fmaxf(v.w, 0.f);
                }
                float f[4] = {v.x, v.y, v.z, v.w};
#pragma unroll
                for (int e = 0; e < 4; e++) {
                    unsigned short hi, lo;
                    split_bf16(f[e], hi, lo);
                    As_hi[ar][ak + q * 4 + e] = hi;
                    As_lo[ar][ak + q * 4 + e] = lo;
                }
            }
        }
        // ---- load & convert B chunk into [n][k] transposed ----
        {
#pragma unroll
            for (int q = 0; q < 4; q++) {
                float4 v = *(const float4*)(bptr + (size_t)(kt + bkl) * ldb + q * 4);
                float f[4] = {v.x, v.y, v.z, v.w};
#pragma unroll
                for (int e = 0; e < 4; e++) {
                    unsigned short hi, lo;
                    split_bf16(f[e], hi, lo);
                    int n = bnb + q * 4 + e;
                    Bs_hi[n][bkl] = hi;
                    Bs_lo[n][bkl] = lo;
                }
            }
        }
        __syncthreads();

        // ---- compute: 2 k-steps of 16 ----
#pragma unroll
        for (int ks = 0; ks < 2; ks++) {
            const int k0 = ks * 16;
            // A fragments (2 m-frags, hi & lo)
            uint32_t ah[2][4], al[2][4];
#pragma unroll
            for (int mf = 0; mf < 2; mf++) {
                const int r0 = warp_m + mf * 16 + g;
                const int c0 = k0 + 2 * tg;
                ah[mf][0] = *(const uint32_t*)&As_hi[r0][c0];
                ah[mf][1] = *(const uint32_t*)&As_hi[r0 + 8][c0];
                ah[mf][2] = *(const uint32_t*)&As_hi[r0][c0 + 8];
                ah[mf][3] = *(const uint32_t*)&As_hi[r0 + 8][c0 + 8];
                al[mf][0] = *(const uint32_t*)&As_lo[r0][c0];
                al[mf][1] = *(const uint32_t*)&As_lo[r0 + 8][c0];
                al[mf][2] = *(const uint32_t*)&As_lo[r0][c0 + 8];
                al[mf][3] = *(const uint32_t*)&As_lo[r0 + 8][c0 + 8];
            }
#pragma unroll
            for (int nf = 0; nf < 8; nf++) {
                const int n = warp_n + nf * 8 + g;
                const int c0 = k0 + 2 * tg;
                uint32_t bh0 = *(const uint32_t*)&Bs_hi[n][c0];
                uint32_t bh1 = *(const uint32_t*)&Bs_hi[n][c0 + 8];
                uint32_t bl0 = *(const uint32_t*)&Bs_lo[n][c0];
                uint32_t bl1 = *(const uint32_t*)&Bs_lo[n][c0 + 8];
#pragma unroll
                for (int mf = 0; mf < 2; mf++) {
                    MMA_BF16(acc[mf][nf][0], acc[mf][nf][1], acc[mf][nf][2], acc[mf][nf][3],
                             ah[mf][0], ah[mf][1], ah[mf][2], ah[mf][3], bh0, bh1);
                    MMA_BF16(acc[mf][nf][0], acc[mf][nf][1], acc[mf][nf][2], acc[mf][nf][3],
                             ah[mf][0], ah[mf][1], ah[mf][2], ah[mf][3], bl0, bl1);
                    MMA_BF16(acc[mf][nf][0], acc[mf][nf][1], acc[mf][nf][2], acc[mf][nf][3],
                             al[mf][0], al[mf][1], al[mf][2], al[mf][3], bh0, bh1);
                }
            }
        }
    }

    // ---- epilogue: fp32 accumulators -> C (row stride 128) ----
#pragma unroll
    for (int mf = 0; mf < 2; mf++) {
#pragma unroll
        for (int nf = 0; nf < 8; nf++) {
            const int row0 = blockRow + warp_m + mf * 16 + g;
            const int col = warp_n + nf * 8 + 2 * tg;
            if (row0 < M) {
                float2 v = make_float2(acc[mf][nf][0], acc[mf][nf][1]);
                *(float2*)(C + (size_t)row0 * 128 + col) = v;
            }
            if (row0 + 8 < M) {
                float2 v = make_float2(acc[mf][nf][2], acc[mf][nf][3]);
                *(float2*)(C + (size_t)(row0 + 8) * 128 + col) = v;
            }
        }
    }
}

// ---------------------------------------------------------------------------
// CSR propagation: warp per node, lane owns 4 channels. No atomics.
// ---------------------------------------------------------------------------
__global__ __launch_bounds__(256) void k_prop_csr(
    const float* __restrict__ H,
    const float* __restrict__ b,
    float* __restrict__ out)
{
    int warp = (blockIdx.x * blockDim.x + threadIdx.x) >> 5;
    if (warp >= NN) return;
    int lane = threadIdx.x & 31;

    float di = g_dinv[warp];
    float s = di * di;
    float4 bb = ((const float4*)b)[lane];
    float4 v = ((const float4*)(H + (size_t)warp * HID))[lane];
    float ax = fmaf(v.x, s, bb.x);
    float ay = fmaf(v.y, s, bb.y);
    float az = fmaf(v.z, s, bb.z);
    float aw = fmaf(v.w, s, bb.w);

    int e = g_off[warp];
    const int end = g_off[warp + 1];
    for (; e + 1 < end; e += 2) {
        int s0 = g_es[e],     s1 = g_es[e + 1];
        float n0 = g_en[e],   n1 = g_en[e + 1];
        float4 v0 = ((const float4*)(H + (size_t)s0 * HID))[lane];
        float4 v1 = ((const float4*)(H + (size_t)s1 * HID))[lane];
        ax = fmaf(v0.x, n0, ax); ay = fmaf(v0.y, n0, ay);
        az = fmaf(v0.z, n0, az); aw = fmaf(v0.w, n0, aw);
        ax = fmaf(v1.x, n1, ax); ay = fmaf(v1.y, n1, ay);
        az = fmaf(v1.z, n1, az); aw = fmaf(v1.w, n1, aw);
    }
    if (e < end) {
        int s0 = g_es[e];
        float n0 = g_en[e];
        float4 v0 = ((const float4*)(H + (size_t)s0 * HID))[lane];
        ax = fmaf(v0.x, n0, ax); ay = fmaf(v0.y, n0, ay);
        az = fmaf(v0.z, n0, az); aw = fmaf(v0.w, n0, aw);
    }

    ((float4*)(out + (size_t)warp * HID))[lane] = make_float4(ax, ay, az, aw);
}

__global__ __launch_bounds__(256) void k_prop_csr_out(
    const float* __restrict__ H,
    const float* __restrict__ bmu,
    const float* __restrict__ blv,
    float* __restrict__ out)
{
    int warp = (blockIdx.x * blockDim.x + threadIdx.x) >> 5;
    if (warp >= NN) return;
    int lane = threadIdx.x & 31;

    float di = g_dinv[warp];
    float s = di * di;
    float4 bb;
    float* dstp;
    if (lane < 16) {
        bb = ((const float4*)bmu)[lane];
        dstp = out + (size_t)warp * 64 + lane * 4;
    } else {
        bb = ((const float4*)blv)[lane - 16];
        dstp = out + (size_t)NN * 64 + (size_t)warp * 64 + (lane - 16) * 4;
    }
    float4 v = ((const float4*)(H + (size_t)warp * HID))[lane];
    float ax = fmaf(v.x, s, bb.x);
    float ay = fmaf(v.y, s, bb.y);
    float az = fmaf(v.z, s, bb.z);
    float aw = fmaf(v.w, s, bb.w);

    int e = g_off[warp];
    const int end = g_off[warp + 1];
    for (; e + 1 < end; e += 2) {
        int s0 = g_es[e],     s1 = g_es[e + 1];
        float n0 = g_en[e],   n1 = g_en[e + 1];
        float4 v0 = ((const float4*)(H + (size_t)s0 * HID))[lane];
        float4 v1 = ((const float4*)(H + (size_t)s1 * HID))[lane];
        ax = fmaf(v0.x, n0, ax); ay = fmaf(v0.y, n0, ay);
        az = fmaf(v0.z, n0, az); aw = fmaf(v0.w, n0, aw);
        ax = fmaf(v1.x, n1, ax); ay = fmaf(v1.y, n1, ay);
        az = fmaf(v1.z, n1, az); aw = fmaf(v1.w, n1, aw);
    }
    if (e < end) {
        int s0 = g_es[e];
        float n0 = g_en[e];
        float4 v0 = ((const float4*)(H + (size_t)s0 * HID))[lane];
        ax = fmaf(v0.x, n0, ax); ay = fmaf(v0.y, n0, ay);
        az = fmaf(v0.z, n0, az); aw = fmaf(v0.w, n0, aw);
    }

    *(float4*)dstp = make_float4(ax, ay, az, aw);
}

// ---------------------------------------------------------------------------
extern "C" void kernel_launch(void* const* d_in, const int* in_sizes, int n_in,
                              void* d_out, int out_size)
{
    const float* x   = (const float*)d_in[0];
    const int*   ei  = (const int*)d_in[1];
    const float* W1  = (const float*)d_in[2];
    const float* b1  = (const float*)d_in[3];
    const float* Wmu = (const float*)d_in[4];
    const float* bmu = (const float*)d_in[5];
    const float* Wlv = (const float*)d_in[6];
    const float* blv = (const float*)d_in[7];
    float* out = (float*)d_out;

    const int* src = ei;
    const int* dst = ei + NE;

    float *h_ptr, *p_ptr;
    cudaGetSymbolAddress((void**)&h_ptr, g_h);
    cudaGetSymbolAddress((void**)&p_ptr, g_p);

    const int TB = 256;

    // --- CSR build ---
    k_cnt_zero<<<(NN + TB - 1) / TB, TB>>>();
    k_count<<<(NE + TB - 1) / TB, TB>>>(dst);
    k_dinv<<<(NN + TB - 1) / TB, TB>>>();
    k_blocksum<<<NB, 1024>>>();
    k_bscan<<<1, 128>>>();
    k_offsets<<<NB, 1024>>>();
    k_scatter<<<(NE + TB - 1) / TB, TB>>>(src, dst);

    // --- Layer 1: h1 = x @ W1 (tensor cores, bf16 split) ---
    tgemm128<INC, false><<<(NN + 127) / 128, 256>>>(x, W1, W1 + 64, 128, h_ptr, NN);

    // --- Propagate hidden (CSR, no atomics) ---
    k_prop_csr<<<(NN * 32 + TB - 1) / TB, TB>>>(h_ptr, b1, p_ptr);

    // --- Layer 2 pre: h2 = relu(p) @ [W_mu | W_logvar] ---
    tgemm128<HID, true><<<(NN + 127) / 128, 256>>>(p_ptr, Wmu, Wlv, 64, h_ptr, NN);

    // --- Propagate to split output ---
    k_prop_csr_out<<<(NN * 32 + TB - 1) / TB, TB>>>(h_ptr, bmu, blv, out);
}

// round 5
// speedup vs baseline: 1.2540x; 1.2540x over previous
#include <cuda_runtime.h>
#include <cuda_bf16.h>
#include <cstdint>

#define NN 100000
#define NE 640000
#define INC 256
#define HID 128
#define NB  ((NN + 1023) / 1024)

// Scratch (__device__ globals — allocation-free rule)
__device__ float g_h[(size_t)NN * HID];          // GEMM2 output (fp32)
__device__ __nv_bfloat16 g_xhi[(size_t)NN * INC];
__device__ __nv_bfloat16 g_xlo[(size_t)NN * INC];
__device__ __nv_bfloat16 g_hhi[(size_t)NN * HID]; // relu(p) split, by prop1
__device__ __nv_bfloat16 g_hlo[(size_t)NN * HID];
__device__ __nv_bfloat16 g_w1hi[INC * HID];      // [n=128][k=256]
__device__ __nv_bfloat16 g_w1lo[INC * HID];
__device__ __nv_bfloat16 g_w2hi[HID * HID];      // [n=128][k=128]
__device__ __nv_bfloat16 g_w2lo[HID * HID];
__device__ float g_dinv[NN];
__device__ int   g_cnt[NN];
__device__ int   g_off[NN + 1];
__device__ int   g_cursor[NN];
__device__ int   g_es[NE];
__device__ float g_en[NE];
__device__ int   g_bsum[128];

__device__ __forceinline__ void split_bf16(float x, unsigned short& hi, unsigned short& lo) {
    __nv_bfloat16 h = __float2bfloat16(x);
    float hf = __bfloat162float(h);
    __nv_bfloat16 l = __float2bfloat16(x - hf);
    hi = *reinterpret_cast<unsigned short*>(&h);
    lo = *reinterpret_cast<unsigned short*>(&l);
}

// ---------------------------------------------------------------------------
// CSR construction
// ---------------------------------------------------------------------------
__global__ void k_cnt_zero() {
    int n = blockIdx.x * blockDim.x + threadIdx.x;
    if (n < NN) g_cnt[n] = 0;
}
__global__ void k_count(const int* __restrict__ dst) {
    int e = blockIdx.x * blockDim.x + threadIdx.x;
    if (e < NE) atomicAdd(&g_cnt[dst[e]], 1);
}
__global__ void k_dinv() {
    int n = blockIdx.x * blockDim.x + threadIdx.x;
    if (n < NN) g_dinv[n] = rsqrtf(1.0f + (float)g_cnt[n]);
}
__global__ __launch_bounds__(1024) void k_blocksum() {
    __shared__ int sm[1024];
    int i = blockIdx.x * 1024 + threadIdx.x;
    int v = (i < NN) ? g_cnt[i] : 0;
    sm[threadIdx.x] = v;
    __syncthreads();
#pragma unroll
    for (int d = 512; d > 0; d >>= 1) {
        if (threadIdx.x < d) sm[threadIdx.x] += sm[threadIdx.x + d];
        __syncthreads();
    }
    if (threadIdx.x == 0) g_bsum[blockIdx.x] = sm[0];
}
__global__ void k_bscan() {
    __shared__ int sm[128];
    int t = threadIdx.x;
    int v = (t < NB) ? g_bsum[t] : 0;
    sm[t] = v;
    __syncthreads();
#pragma unroll
    for (int d = 1; d < 128; d <<= 1) {
        int x = (t >= d) ? sm[t - d] : 0;
        __syncthreads();
        sm[t] += x;
        __syncthreads();
    }
    if (t < 128) g_bsum[t] = sm[t] - v;
}
__global__ __launch_bounds__(1024) void k_offsets() {
    __shared__ int sm[1024];
    int i = blockIdx.x * 1024 + threadIdx.x;
    int v = (i < NN) ? g_cnt[i] : 0;
    sm[threadIdx.x] = v;
    __syncthreads();
#pragma unroll
    for (int d = 1; d < 1024; d <<= 1) {
        int x = (threadIdx.x >= d) ? sm[threadIdx.x - d] : 0;
        __syncthreads();
        sm[threadIdx.x] += x;
        __syncthreads();
    }
    if (i < NN) {
        int off = g_bsum[blockIdx.x] + sm[threadIdx.x] - v;
        g_off[i] = off;
        g_cursor[i] = off;
    }
    if (i == 0) g_off[NN] = NE;
}
__global__ void k_scatter(const int* __restrict__ src, const int* __restrict__ dst) {
    int e = blockIdx.x * blockDim.x + threadIdx.x;
    if (e >= NE) return;
    int s = src[e], d = dst[e];
    int pos = atomicAdd(&g_cursor[d], 1);
    g_es[pos] = s;
    g_en[pos] = g_dinv[s] * g_dinv[d];
}

// ---------------------------------------------------------------------------
// Pre-conversion kernels
// ---------------------------------------------------------------------------
__global__ void k_convx(const float* __restrict__ x) {
    int i = blockIdx.x * blockDim.x + threadIdx.x;   // over NN*INC/4
    if (i >= NN * (INC / 4)) return;
    float4 v = ((const float4*)x)[i];
    unsigned short h[4], l[4];
    split_bf16(v.x, h[0], l[0]); split_bf16(v.y, h[1], l[1]);
    split_bf16(v.z, h[2], l[2]); split_bf16(v.w, h[3], l[3]);
    ((uint2*)g_xhi)[i] = make_uint2(h[0] | ((uint32_t)h[1] << 16), h[2] | ((uint32_t)h[3] << 16));
    ((uint2*)g_xlo)[i] = make_uint2(l[0] | ((uint32_t)l[1] << 16), l[2] | ((uint32_t)l[3] << 16));
}

// W1 [k=256][n=128] -> g_w1 [n][k]
__global__ void k_convw1(const float* __restrict__ W1) {
    int i = blockIdx.x * blockDim.x + threadIdx.x;   // i = n*256 + k
    if (i >= INC * HID) return;
    int n = i >> 8, k = i & 255;
    unsigned short h, l;
    split_bf16(W1[k * 128 + n], h, l);
    g_w1hi[i] = *(__nv_bfloat16*)&h;
    g_w1lo[i] = *(__nv_bfloat16*)&l;
}

// [Wmu | Wlv] each [k=128][n=64] -> g_w2 [n=128][k=128]
__global__ void k_convw2(const float* __restrict__ Wmu, const float* __restrict__ Wlv) {
    int i = blockIdx.x * blockDim.x + threadIdx.x;   // i = n*128 + k
    if (i >= HID * HID) return;
    int n = i >> 7, k = i & 127;
    float v = (n < 64) ? Wmu[k * 64 + n] : Wlv[k * 64 + (n - 64)];
    unsigned short h, l;
    split_bf16(v, h, l);
    g_w2hi[i] = *(__nv_bfloat16*)&h;
    g_w2lo[i] = *(__nv_bfloat16*)&l;
}

// ---------------------------------------------------------------------------
// Tensor-core GEMM on preconverted bf16 hi/lo operands.
// C[M,128] = A @ B^T where A planes are [M][KT], B planes are [128 n][KT].
// 3-pass split: hi*hi + hi*lo + lo*hi, fp32 accumulate.
// Block 256 thr (8 warps 4Mx2N), tile 128x128x32, warp 32x64.
// ---------------------------------------------------------------------------
#define MMA_BF16(c0,c1,c2,c3,a0,a1,a2,a3,b0,b1)                                  \
    asm volatile("mma.sync.aligned.m16n8k16.row.col.f32.bf16.bf16.f32 "          \
        "{%0,%1,%2,%3}, {%4,%5,%6,%7}, {%8,%9}, {%0,%1,%2,%3};"                  \
        : "+f"(c0), "+f"(c1), "+f"(c2), "+f"(c3)                                  \
        : "r"(a0), "r"(a1), "r"(a2), "r"(a3), "r"(b0), "r"(b1))

#define LDA 40

template <int KT>
__global__ __launch_bounds__(256, 2) void tgemm_bf16(
    const __nv_bfloat16* __restrict__ Ahi, const __nv_bfloat16* __restrict__ Alo,
    const __nv_bfloat16* __restrict__ Bhi, const __nv_bfloat16* __restrict__ Blo,
    float* __restrict__ C, int M)
{
    __shared__ unsigned short As_hi[128][LDA];
    __shared__ unsigned short As_lo[128][LDA];
    __shared__ unsigned short Bs_hi[128][LDA];
    __shared__ unsigned short Bs_lo[128][LDA];

    const int t = threadIdx.x;
    const int w = t >> 5;
    const int lane = t & 31;
    const int g = lane >> 2;
    const int tg = lane & 3;
    const int warp_m = (w & 3) * 32;
    const int warp_n = (w >> 2) * 64;
    const int blockRow = blockIdx.x * 128;

    // staging mapping (same for A and B): row = t>>1, k-offset (t&1)*16
    const int lr = t >> 1;
    const int lk = (t & 1) * 16;
    const int grow = blockRow + lr;
    const bool arow_ok = (grow < M);
    const __nv_bfloat16* aphi = Ahi + (size_t)grow * KT + lk;
    const __nv_bfloat16* aplo = Alo + (size_t)grow * KT + lk;
    const __nv_bfloat16* bphi = Bhi + (size_t)lr * KT + lk;
    const __nv_bfloat16* bplo = Blo + (size_t)lr * KT + lk;

    float acc[2][8][4];
#pragma unroll
    for (int i = 0; i < 2; i++)
#pragma unroll
        for (int j = 0; j < 8; j++)
#pragma unroll
            for (int k = 0; k < 4; k++) acc[i][j][k] = 0.0f;

    const uint4 z4 = make_uint4(0, 0, 0, 0);

#pragma unroll 1
    for (int kt = 0; kt < KT; kt += 32) {
        uint4 ah0 = z4, ah1 = z4, al0 = z4, al1 = z4;
        if (arow_ok) {
            ah0 = *(const uint4*)(aphi + kt);
            ah1 = *(const uint4*)(aphi + kt + 8);
            al0 = *(const uint4*)(aplo + kt);
            al1 = *(const uint4*)(aplo + kt + 8);
        }
        uint4 bh0 = *(const uint4*)(bphi + kt);
        uint4 bh1 = *(const uint4*)(bphi + kt + 8);
        uint4 bl0 = *(const uint4*)(bplo + kt);
        uint4 bl1 = *(const uint4*)(bplo + kt + 8);

        __syncthreads();
        *(uint4*)&As_hi[lr][lk]     = ah0;
        *(uint4*)&As_hi[lr][lk + 8] = ah1;
        *(uint4*)&As_lo[lr][lk]     = al0;
        *(uint4*)&As_lo[lr][lk + 8] = al1;
        *(uint4*)&Bs_hi[lr][lk]     = bh0;
        *(uint4*)&Bs_hi[lr][lk + 8] = bh1;
        *(uint4*)&Bs_lo[lr][lk]     = bl0;
        *(uint4*)&Bs_lo[lr][lk + 8] = bl1;
        __syncthreads();

#pragma unroll
        for (int ks = 0; ks < 2; ks++) {
            const int k0 = ks * 16;
            const int c0 = k0 + 2 * tg;
            uint32_t ah[2][4], al[2][4];
#pragma unroll
            for (int mf = 0; mf < 2; mf++) {
                const int r0 = warp_m + mf * 16 + g;
                ah[mf][0] = *(const uint32_t*)&As_hi[r0][c0];
                ah[mf][1] = *(const uint32_t*)&As_hi[r0 + 8][c0];
                ah[mf][2] = *(const uint32_t*)&As_hi[r0][c0 + 8];
                ah[mf][3] = *(const uint32_t*)&As_hi[r0 + 8][c0 + 8];
                al[mf][0] = *(const uint32_t*)&As_lo[r0][c0];
                al[mf][1] = *(const uint32_t*)&As_lo[r0 + 8][c0];
                al[mf][2] = *(const uint32_t*)&As_lo[r0][c0 + 8];
                al[mf][3] = *(const uint32_t*)&As_lo[r0 + 8][c0 + 8];
            }
#pragma unroll
            for (int nf = 0; nf < 8; nf++) {
                const int n = warp_n + nf * 8 + g;
                uint32_t vbh0 = *(const uint32_t*)&Bs_hi[n][c0];
                uint32_t vbh1 = *(const uint32_t*)&Bs_hi[n][c0 + 8];
                uint32_t vbl0 = *(const uint32_t*)&Bs_lo[n][c0];
                uint32_t vbl1 = *(const uint32_t*)&Bs_lo[n][c0 + 8];
#pragma unroll
                for (int mf = 0; mf < 2; mf++) {
                    MMA_BF16(acc[mf][nf][0], acc[mf][nf][1], acc[mf][nf][2], acc[mf][nf][3],
                             ah[mf][0], ah[mf][1], ah[mf][2], ah[mf][3], vbh0, vbh1);
                    MMA_BF16(acc[mf][nf][0], acc[mf][nf][1], acc[mf][nf][2], acc[mf][nf][3],
                             ah[mf][0], ah[mf][1], ah[mf][2], ah[mf][3], vbl0, vbl1);
                    MMA_BF16(acc[mf][nf][0], acc[mf][nf][1], acc[mf][nf][2], acc[mf][nf][3],
                             al[mf][0], al[mf][1], al[mf][2], al[mf][3], vbh0, vbh1);
                }
            }
        }
    }

#pragma unroll
    for (int mf = 0; mf < 2; mf++) {
#pragma unroll
        for (int nf = 0; nf < 8; nf++) {
            const int row0 = blockRow + warp_m + mf * 16 + g;
            const int col = warp_n + nf * 8 + 2 * tg;
            if (row0 < M) {
                *(float2*)(C + (size_t)row0 * 128 + col) =
                    make_float2(acc[mf][nf][0], acc[mf][nf][1]);
            }
            if (row0 + 8 < M) {
                *(float2*)(C + (size_t)(row0 + 8) * 128 + col) =
                    make_float2(acc[mf][nf][2], acc[mf][nf][3]);
            }
        }
    }
}

// ---------------------------------------------------------------------------
// Layer-1 propagation fused with ReLU + bf16 split output (feeds GEMM2).
// Reads GEMM1 output H (fp32), CSR; writes g_hhi/g_hlo.
// ---------------------------------------------------------------------------
__global__ __launch_bounds__(256) void k_prop_csr_split(
    const float* __restrict__ H,
    const float* __restrict__ b)
{
    int warp = (blockIdx.x * blockDim.x + threadIdx.x) >> 5;
    if (warp >= NN) return;
    int lane = threadIdx.x & 31;

    float di = g_dinv[warp];
    float s = di * di;
    float4 bb = ((const float4*)b)[lane];
    float4 v = ((const float4*)(H + (size_t)warp * HID))[lane];
    float ax = fmaf(v.x, s, bb.x);
    float ay = fmaf(v.y, s, bb.y);
    float az = fmaf(v.z, s, bb.z);
    float aw = fmaf(v.w, s, bb.w);

    int e = g_off[warp];
    const int end = g_off[warp + 1];
    for (; e + 1 < end; e += 2) {
        int s0 = g_es[e],     s1 = g_es[e + 1];
        float n0 = g_en[e],   n1 = g_en[e + 1];
        float4 v0 = ((const float4*)(H + (size_t)s0 * HID))[lane];
        float4 v1 = ((const float4*)(H + (size_t)s1 * HID))[lane];
        ax = fmaf(v0.x, n0, ax); ay = fmaf(v0.y, n0, ay);
        az = fmaf(v0.z, n0, az); aw = fmaf(v0.w, n0, aw);
        ax = fmaf(v1.x, n1, ax); ay = fmaf(v1.y, n1, ay);
        az = fmaf(v1.z, n1, az); aw = fmaf(v1.w, n1, aw);
    }
    if (e < end) {
        int s0 = g_es[e];
        float n0 = g_en[e];
        float4 v0 = ((const float4*)(H + (size_t)s0 * HID))[lane];
        ax = fmaf(v0.x, n0, ax); ay = fmaf(v0.y, n0, ay);
        az = fmaf(v0.z, n0, az); aw = fmaf(v0.w, n0, aw);
    }

    // ReLU + split
    ax = fmaxf(ax, 0.f); ay = fmaxf(ay, 0.f);
    az = fmaxf(az, 0.f); aw = fmaxf(aw, 0.f);
    unsigned short h[4], l[4];
    split_bf16(ax, h[0], l[0]); split_bf16(ay, h[1], l[1]);
    split_bf16(az, h[2], l[2]); split_bf16(aw, h[3], l[3]);
    size_t o = (size_t)warp * HID + lane * 4;
    *(uint2*)(g_hhi + o) = make_uint2(h[0] | ((uint32_t)h[1] << 16), h[2] | ((uint32_t)h[3] << 16));
    *(uint2*)(g_hlo + o) = make_uint2(l[0] | ((uint32_t)l[1] << 16), l[2] | ((uint32_t)l[3] << 16));
}

// Layer-2 propagation to split output (mu | logvar)
__global__ __launch_bounds__(256) void k_prop_csr_out(
    const float* __restrict__ H,
    const float* __restrict__ bmu,
    const float* __restrict__ blv,
    float* __restrict__ out)
{
    int warp = (blockIdx.x * blockDim.x + threadIdx.x) >> 5;
    if (warp >= NN) return;
    int lane = threadIdx.x & 31;

    float di = g_dinv[warp];
    float s = di * di;
    float4 bb;
    float* dstp;
    if (lane < 16) {
        bb = ((const float4*)bmu)[lane];
        dstp = out + (size_t)warp * 64 + lane * 4;
    } else {
        bb = ((const float4*)blv)[lane - 16];
        dstp = out + (size_t)NN * 64 + (size_t)warp * 64 + (lane - 16) * 4;
    }
    float4 v = ((const float4*)(H + (size_t)warp * HID))[lane];
    float ax = fmaf(v.x, s, bb.x);
    float ay = fmaf(v.y, s, bb.y);
    float az = fmaf(v.z, s, bb.z);
    float aw = fmaf(v.w, s, bb.w);

    int e = g_off[warp];
    const int end = g_off[warp + 1];
    for (; e + 1 < end; e += 2) {
        int s0 = g_es[e],     s1 = g_es[e + 1];
        float n0 = g_en[e],   n1 = g_en[e + 1];
        float4 v0 = ((const float4*)(H + (size_t)s0 * HID))[lane];
        float4 v1 = ((const float4*)(H + (size_t)s1 * HID))[lane];
        ax = fmaf(v0.x, n0, ax); ay = fmaf(v0.y, n0, ay);
        az = fmaf(v0.z, n0, az); aw = fmaf(v0.w, n0, aw);
        ax = fmaf(v1.x, n1, ax); ay = fmaf(v1.y, n1, ay);
        az = fmaf(v1.z, n1, az); aw = fmaf(v1.w, n1, aw);
    }
    if (e < end) {
        int s0 = g_es[e];
        float n0 = g_en[e];
        float4 v0 = ((const float4*)(H + (size_t)s0 * HID))[lane];
        ax = fmaf(v0.x, n0, ax); ay = fmaf(v0.y, n0, ay);
        az = fmaf(v0.z, n0, az); aw = fmaf(v0.w, n0, aw);
    }

    *(float4*)dstp = make_float4(ax, ay, az, aw);
}

// ---------------------------------------------------------------------------
extern "C" void kernel_launch(void* const* d_in, const int* in_sizes, int n_in,
                              void* d_out, int out_size)
{
    const float* x   = (const float*)d_in[0];
    const int*   ei  = (const int*)d_in[1];
    const float* W1  = (const float*)d_in[2];
    const float* b1  = (const float*)d_in[3];
    const float* Wmu = (const float*)d_in[4];
    const float* bmu = (const float*)d_in[5];
    const float* Wlv = (const float*)d_in[6];
    const float* blv = (const float*)d_in[7];
    float* out = (float*)d_out;

    const int* src = ei;
    const int* dst = ei + NE;

    float *h_ptr;
    cudaGetSymbolAddress((void**)&h_ptr, g_h);
    __nv_bfloat16 *xhi, *xlo, *hhi, *hlo, *w1hi, *w1lo, *w2hi, *w2lo;
    cudaGetSymbolAddress((void**)&xhi, g_xhi);
    cudaGetSymbolAddress((void**)&xlo, g_xlo);
    cudaGetSymbolAddress((void**)&hhi, g_hhi);
    cudaGetSymbolAddress((void**)&hlo, g_hlo);
    cudaGetSymbolAddress((void**)&w1hi, g_w1hi);
    cudaGetSymbolAddress((void**)&w1lo, g_w1lo);
    cudaGetSymbolAddress((void**)&w2hi, g_w2hi);
    cudaGetSymbolAddress((void**)&w2lo, g_w2lo);

    const int TB = 256;

    // --- CSR build ---
    k_cnt_zero<<<(NN + TB - 1) / TB, TB>>>();
    k_count<<<(NE + TB - 1) / TB, TB>>>(dst);
    k_dinv<<<(NN + TB - 1) / TB, TB>>>();
    k_blocksum<<<NB, 1024>>>();
    k_bscan<<<1, 128>>>();
    k_offsets<<<NB, 1024>>>();
    k_scatter<<<(NE + TB - 1) / TB, TB>>>(src, dst);

    // --- Pre-conversions ---
    k_convx<<<(NN * (INC / 4) + TB - 1) / TB, TB>>>(x);
    k_convw1<<<(INC * HID + TB - 1) / TB, TB>>>(W1);
    k_convw2<<<(HID * HID + TB - 1) / TB, TB>>>(Wmu, Wlv);

    // --- Layer 1: h1 = x @ W1 (tensor cores, preconverted bf16 split) ---
    tgemm_bf16<INC><<<(NN + 127) / 128, 256>>>(xhi, xlo, w1hi, w1lo, h_ptr, NN);

    // --- Propagate + ReLU + split (feeds GEMM2) ---
    k_prop_csr_split<<<(NN * 32 + TB - 1) / TB, TB>>>(h_ptr, b1);

    // --- Layer 2: h2 = relu(p) @ [W_mu | W_logvar] ---
    tgemm_bf16<HID><<<(NN + 127) / 128, 256>>>(hhi, hlo, w2hi, w2lo, h_ptr, NN);

    // --- Propagate to split output ---
    k_prop_csr_out<<<(NN * 32 + TB - 1) / TB, TB>>>(h_ptr, bmu, blv, out);
}

// round 7
// speedup vs baseline: 1.6097x; 1.2836x over previous
#include <cuda_runtime.h>
#include <cuda_bf16.h>
#include <cstdint>

#define NN 100000
#define NE 640000
#define INC 256
#define HID 128
#define NB  ((NN + 1023) / 1024)

// ---------------- scratch (__device__ globals) ----------------
__device__ float g_h[(size_t)NN * HID];
__device__ __nv_bfloat16 g_xhi[(size_t)NN * INC];
__device__ __nv_bfloat16 g_xlo[(size_t)NN * INC];
__device__ __nv_bfloat16 g_hhi[(size_t)NN * HID];
__device__ __nv_bfloat16 g_hlo[(size_t)NN * HID];
__device__ __nv_bfloat16 g_w1hi[INC * HID];      // [n=128][k=256]
__device__ __nv_bfloat16 g_w1lo[INC * HID];
__device__ __nv_bfloat16 g_w2hi[HID * HID];      // [n=128][k=128]
__device__ __nv_bfloat16 g_w2lo[HID * HID];
__device__ float g_dinv[NN];
__device__ int   g_cnt[NN];
__device__ int   g_off[NN + 1];
__device__ int   g_cursor[NN];
__device__ int   g_es[NE];
__device__ float g_en[NE];
__device__ int   g_bsum[128];

__device__ __forceinline__ void split_bf16(float x, unsigned short& hi, unsigned short& lo) {
    __nv_bfloat16 h = __float2bfloat16(x);
    float hf = __bfloat162float(h);
    __nv_bfloat16 l = __float2bfloat16(x - hf);
    hi = *reinterpret_cast<unsigned short*>(&h);
    lo = *reinterpret_cast<unsigned short*>(&l);
}

// ---------------------------------------------------------------------------
// CSR construction
// ---------------------------------------------------------------------------
__global__ void k_cnt_zero() {
    int n = blockIdx.x * blockDim.x + threadIdx.x;
    if (n < NN) g_cnt[n] = 0;
}
__global__ void k_count(const int* __restrict__ dst) {
    int e = blockIdx.x * blockDim.x + threadIdx.x;
    if (e < NE) atomicAdd(&g_cnt[dst[e]], 1);
}
__global__ void k_dinv() {
    int n = blockIdx.x * blockDim.x + threadIdx.x;
    if (n < NN) g_dinv[n] = rsqrtf(1.0f + (float)g_cnt[n]);
}
__global__ __launch_bounds__(1024) void k_blocksum() {
    __shared__ int sm[1024];
    int i = blockIdx.x * 1024 + threadIdx.x;
    int v = (i < NN) ? g_cnt[i] : 0;
    sm[threadIdx.x] = v;
    __syncthreads();
#pragma unroll
    for (int d = 512; d > 0; d >>= 1) {
        if (threadIdx.x < d) sm[threadIdx.x] += sm[threadIdx.x + d];
        __syncthreads();
    }
    if (threadIdx.x == 0) g_bsum[blockIdx.x] = sm[0];
}
__global__ void k_bscan() {
    __shared__ int sm[128];
    int t = threadIdx.x;
    int v = (t < NB) ? g_bsum[t] : 0;
    sm[t] = v;
    __syncthreads();
#pragma unroll
    for (int d = 1; d < 128; d <<= 1) {
        int x = (t >= d) ? sm[t - d] : 0;
        __syncthreads();
        sm[t] += x;
        __syncthreads();
    }
    if (t < 128) g_bsum[t] = sm[t] - v;
}
__global__ __launch_bounds__(1024) void k_offsets() {
    __shared__ int sm[1024];
    int i = blockIdx.x * 1024 + threadIdx.x;
    int v = (i < NN) ? g_cnt[i] : 0;
    sm[threadIdx.x] = v;
    __syncthreads();
#pragma unroll
    for (int d = 1; d < 1024; d <<= 1) {
        int x = (threadIdx.x >= d) ? sm[threadIdx.x - d] : 0;
        __syncthreads();
        sm[threadIdx.x] += x;
        __syncthreads();
    }
    if (i < NN) {
        int off = g_bsum[blockIdx.x] + sm[threadIdx.x] - v;
        g_off[i] = off;
        g_cursor[i] = off;
    }
    if (i == 0) g_off[NN] = NE;
}
__global__ void k_scatter(const int* __restrict__ src, const int* __restrict__ dst) {
    int e = blockIdx.x * blockDim.x + threadIdx.x;
    if (e >= NE) return;
    int s = src[e], d = dst[e];
    int pos = atomicAdd(&g_cursor[d], 1);
    g_es[pos] = s;
    g_en[pos] = g_dinv[s] * g_dinv[d];
}

// ---------------------------------------------------------------------------
// Pre-conversion kernels
// ---------------------------------------------------------------------------
__global__ void k_convx(const float* __restrict__ x) {
    int i = blockIdx.x * blockDim.x + threadIdx.x;
    if (i >= NN * (INC / 4)) return;
    float4 v = ((const float4*)x)[i];
    unsigned short h[4], l[4];
    split_bf16(v.x, h[0], l[0]); split_bf16(v.y, h[1], l[1]);
    split_bf16(v.z, h[2], l[2]); split_bf16(v.w, h[3], l[3]);
    ((uint2*)g_xhi)[i] = make_uint2(h[0] | ((uint32_t)h[1] << 16), h[2] | ((uint32_t)h[3] << 16));
    ((uint2*)g_xlo)[i] = make_uint2(l[0] | ((uint32_t)l[1] << 16), l[2] | ((uint32_t)l[3] << 16));
}
__global__ void k_convw1(const float* __restrict__ W1) {
    int i = blockIdx.x * blockDim.x + threadIdx.x;   // i = n*256 + k
    if (i >= INC * HID) return;
    int n = i >> 8, k = i & 255;
    unsigned short h, l;
    split_bf16(W1[k * 128 + n], h, l);
    g_w1hi[i] = *(__nv_bfloat16*)&h;
    g_w1lo[i] = *(__nv_bfloat16*)&l;
}
__global__ void k_convw2(const float* __restrict__ Wmu, const float* __restrict__ Wlv) {
    int i = blockIdx.x * blockDim.x + threadIdx.x;   // i = n*128 + k
    if (i >= HID * HID) return;
    int n = i >> 7, k = i & 127;
    float v = (n < 64) ? Wmu[k * 64 + n] : Wlv[k * 64 + (n - 64)];
    unsigned short h, l;
    split_bf16(v, h, l);
    g_w2hi[i] = *(__nv_bfloat16*)&h;
    g_w2lo[i] = *(__nv_bfloat16*)&l;
}

// ---------------------------------------------------------------------------
// mma.sync bf16-split GEMM, restructured:
//  - pass-major MMA ordering (no accumulator RAW serialization)
//  - LDA=36 shorts (72 B) -> <=2-way bank conflicts
//  - double-buffered smem with register prefetch
// C[M,128] = A @ B^T; A planes [M][KT], B planes [128][KT].
// Block 256 thr, 8 warps (4M x 2N), block tile 128x128, chunk k=32.
// ---------------------------------------------------------------------------
#define MMA_BF16(c0,c1,c2,c3,a0,a1,a2,a3,b0,b1)                                  \
    asm volatile("mma.sync.aligned.m16n8k16.row.col.f32.bf16.bf16.f32 "          \
        "{%0,%1,%2,%3}, {%4,%5,%6,%7}, {%8,%9}, {%0,%1,%2,%3};"                  \
        : "+f"(c0), "+f"(c1), "+f"(c2), "+f"(c3)                                  \
        : "r"(a0), "r"(a1), "r"(a2), "r"(a3), "r"(b0), "r"(b1))

#define LDA 36                       // shorts per row (72 B)
#define PLANE_BYTES (128 * LDA * 2)  // 9216 B per buffer
#define OFF_AHI 0
#define OFF_ALO (2 * PLANE_BYTES)
#define OFF_BHI (4 * PLANE_BYTES)
#define OFF_BLO (6 * PLANE_BYTES)
#define SMEM_GEMM (8 * PLANE_BYTES)  // 73728 B

template <int KT>
__global__ __launch_bounds__(256) void tgemm_bf16(
    const __nv_bfloat16* __restrict__ Ahi, const __nv_bfloat16* __restrict__ Alo,
    const __nv_bfloat16* __restrict__ Bhi, const __nv_bfloat16* __restrict__ Blo,
    float* __restrict__ C, int M)
{
    extern __shared__ char sm[];

    const int t = threadIdx.x;
    const int w = t >> 5;
    const int lane = t & 31;
    const int g = lane >> 2;
    const int tg = lane & 3;
    const int warp_m = (w & 3) * 32;
    const int warp_n = (w >> 2) * 64;
    const int blockRow = blockIdx.x * 128;

    // staging mapping: thread loads row lr, shorts [ko, ko+16)
    const int lr = t >> 1;
    const int ko = (t & 1) * 16;
    int grow = blockRow + lr;
    if (grow > M - 1) grow = M - 1;  // clamp; epilogue guards stores
    const __nv_bfloat16* apH = Ahi + (size_t)grow * KT + ko;
    const __nv_bfloat16* apL = Alo + (size_t)grow * KT + ko;
    const __nv_bfloat16* bpH = Bhi + (size_t)lr * KT + ko;
    const __nv_bfloat16* bpL = Blo + (size_t)lr * KT + ko;

    float acc[2][8][4];
#pragma unroll
    for (int i = 0; i < 2; i++)
#pragma unroll
        for (int j = 0; j < 8; j++)
#pragma unroll
            for (int k = 0; k < 4; k++) acc[i][j][k] = 0.0f;

    // prefetch registers (chunk data: 2 x uint4 per plane-side)
    uint4 pah0, pah1, pal0, pal1, pbh0, pbh1, pbl0, pbl1;
    pah0 = *(const uint4*)(apH);     pah1 = *(const uint4*)(apH + 8);
    pal0 = *(const uint4*)(apL);     pal1 = *(const uint4*)(apL + 8);
    pbh0 = *(const uint4*)(bpH);     pbh1 = *(const uint4*)(bpH + 8);
    pbl0 = *(const uint4*)(bpL);     pbl1 = *(const uint4*)(bpL + 8);

    constexpr int NCHUNK = KT / 32;
    int cur = 0;

#pragma unroll 1
    for (int c = 0; c < NCHUNK; c++) {
        // ---- store prefetched chunk into buffer[cur] (uint2, 8B-aligned) ----
        {
            char* base = sm + (size_t)cur * PLANE_BYTES + (size_t)lr * (LDA * 2) + ko * 2;
            *(uint2*)(base + OFF_AHI)      = make_uint2(pah0.x, pah0.y);
            *(uint2*)(base + OFF_AHI + 8)  = make_uint2(pah0.z, pah0.w);
            *(uint2*)(base + OFF_AHI + 16) = make_uint2(pah1.x, pah1.y);
            *(uint2*)(base + OFF_AHI + 24) = make_uint2(pah1.z, pah1.w);
            *(uint2*)(base + OFF_ALO)      = make_uint2(pal0.x, pal0.y);
            *(uint2*)(base + OFF_ALO + 8)  = make_uint2(pal0.z, pal0.w);
            *(uint2*)(base + OFF_ALO + 16) = make_uint2(pal1.x, pal1.y);
            *(uint2*)(base + OFF_ALO + 24) = make_uint2(pal1.z, pal1.w);
            *(uint2*)(base + OFF_BHI)      = make_uint2(pbh0.x, pbh0.y);
            *(uint2*)(base + OFF_BHI + 8)  = make_uint2(pbh0.z, pbh0.w);
            *(uint2*)(base + OFF_BHI + 16) = make_uint2(pbh1.x, pbh1.y);
            *(uint2*)(base + OFF_BHI + 24) = make_uint2(pbh1.z, pbh1.w);
            *(uint2*)(base + OFF_BLO)      = make_uint2(pbl0.x, pbl0.y);
            *(uint2*)(base + OFF_BLO + 8)  = make_uint2(pbl0.z, pbl0.w);
            *(uint2*)(base + OFF_BLO + 16) = make_uint2(pbl1.x, pbl1.y);
            *(uint2*)(base + OFF_BLO + 24) = make_uint2(pbl1.z, pbl1.w);
        }
        __syncthreads();

        // ---- prefetch next chunk (overlaps with MMA below) ----
        if (c + 1 < NCHUNK) {
            const int kt = (c + 1) * 32;
            pah0 = *(const uint4*)(apH + kt);  pah1 = *(const uint4*)(apH + kt + 8);
            pal0 = *(const uint4*)(apL + kt);  pal1 = *(const uint4*)(apL + kt + 8);
            pbh0 = *(const uint4*)(bpH + kt);  pbh1 = *(const uint4*)(bpH + kt + 8);
            pbl0 = *(const uint4*)(bpL + kt);  pbl1 = *(const uint4*)(bpL + kt + 8);
        }

        // ---- compute on buffer[cur]: 2 k-steps of 16 ----
        const unsigned short* sAhi = (const unsigned short*)(sm + OFF_AHI + (size_t)cur * PLANE_BYTES);
        const unsigned short* sAlo = (const unsigned short*)(sm + OFF_ALO + (size_t)cur * PLANE_BYTES);
        const unsigned short* sBhi = (const unsigned short*)(sm + OFF_BHI + (size_t)cur * PLANE_BYTES);
        const unsigned short* sBlo = (const unsigned short*)(sm + OFF_BLO + (size_t)cur * PLANE_BYTES);

#pragma unroll
        for (int ks = 0; ks < 2; ks++) {
            const int c0 = ks * 16 + 2 * tg;
            uint32_t ah[2][4], al[2][4];
#pragma unroll
            for (int mf = 0; mf < 2; mf++) {
                const int r0 = warp_m + mf * 16 + g;
                ah[mf][0] = *(const uint32_t*)&sAhi[(size_t)r0 * LDA + c0];
                ah[mf][1] = *(const uint32_t*)&sAhi[(size_t)(r0 + 8) * LDA + c0];
                ah[mf][2] = *(const uint32_t*)&sAhi[(size_t)r0 * LDA + c0 + 8];
                ah[mf][3] = *(const uint32_t*)&sAhi[(size_t)(r0 + 8) * LDA + c0 + 8];
                al[mf][0] = *(const uint32_t*)&sAlo[(size_t)r0 * LDA + c0];
                al[mf][1] = *(const uint32_t*)&sAlo[(size_t)(r0 + 8) * LDA + c0];
                al[mf][2] = *(const uint32_t*)&sAlo[(size_t)r0 * LDA + c0 + 8];
                al[mf][3] = *(const uint32_t*)&sAlo[(size_t)(r0 + 8) * LDA + c0 + 8];
            }
            // pass-major: consecutive MMAs hit different accumulators
#pragma unroll
            for (int pass = 0; pass < 3; pass++) {
                const unsigned short* sB = (pass == 1) ? sBlo : sBhi;
#pragma unroll
                for (int nf = 0; nf < 8; nf++) {
                    const int n = warp_n + nf * 8 + g;
                    uint32_t b0 = *(const uint32_t*)&sB[(size_t)n * LDA + c0];
                    uint32_t b1 = *(const uint32_t*)&sB[(size_t)n * LDA + c0 + 8];
                    if (pass == 2) {
                        MMA_BF16(acc[0][nf][0], acc[0][nf][1], acc[0][nf][2], acc[0][nf][3],
                                 al[0][0], al[0][1], al[0][2], al[0][3], b0, b1);
                        MMA_BF16(acc[1][nf][0], acc[1][nf][1], acc[1][nf][2], acc[1][nf][3],
                                 al[1][0], al[1][1], al[1][2], al[1][3], b0, b1);
                    } else {
                        MMA_BF16(acc[0][nf][0], acc[0][nf][1], acc[0][nf][2], acc[0][nf][3],
                                 ah[0][0], ah[0][1], ah[0][2], ah[0][3], b0, b1);
                        MMA_BF16(acc[1][nf][0], acc[1][nf][1], acc[1][nf][2], acc[1][nf][3],
                                 ah[1][0], ah[1][1], ah[1][2], ah[1][3], b0, b1);
                    }
                }
            }
        }
        cur ^= 1;
    }

    // ---- epilogue ----
#pragma unroll
    for (int mf = 0; mf < 2; mf++) {
#pragma unroll
        for (int nf = 0; nf < 8; nf++) {
            const int row0 = blockRow + warp_m + mf * 16 + g;
            const int col = warp_n + nf * 8 + 2 * tg;
            if (row0 < M) {
                *(float2*)(C + (size_t)row0 * 128 + col) =
                    make_float2(acc[mf][nf][0], acc[mf][nf][1]);
            }
            if (row0 + 8 < M) {
                *(float2*)(C + (size_t)(row0 + 8) * 128 + col) =
                    make_float2(acc[mf][nf][2], acc[mf][nf][3]);
            }
        }
    }
}

// ---------------------------------------------------------------------------
// CSR propagation kernels
// ---------------------------------------------------------------------------
__global__ __launch_bounds__(256) void k_prop_csr_split(
    const float* __restrict__ H,
    const float* __restrict__ b)
{
    int warp = (blockIdx.x * blockDim.x + threadIdx.x) >> 5;
    if (warp >= NN) return;
    int lane = threadIdx.x & 31;

    float di = g_dinv[warp];
    float s = di * di;
    float4 bb = ((const float4*)b)[lane];
    float4 v = ((const float4*)(H + (size_t)warp * HID))[lane];
    float ax = fmaf(v.x, s, bb.x);
    float ay = fmaf(v.y, s, bb.y);
    float az = fmaf(v.z, s, bb.z);
    float aw = fmaf(v.w, s, bb.w);

    int e = g_off[warp];
    const int end = g_off[warp + 1];
    for (; e + 1 < end; e += 2) {
        int s0 = g_es[e],     s1 = g_es[e + 1];
        float n0 = g_en[e],   n1 = g_en[e + 1];
        float4 v0 = ((const float4*)(H + (size_t)s0 * HID))[lane];
        float4 v1 = ((const float4*)(H + (size_t)s1 * HID))[lane];
        ax = fmaf(v0.x, n0, ax); ay = fmaf(v0.y, n0, ay);
        az = fmaf(v0.z, n0, az); aw = fmaf(v0.w, n0, aw);
        ax = fmaf(v1.x, n1, ax); ay = fmaf(v1.y, n1, ay);
        az = fmaf(v1.z, n1, az); aw = fmaf(v1.w, n1, aw);
    }
    if (e < end) {
        int s0 = g_es[e];
        float n0 = g_en[e];
        float4 v0 = ((const float4*)(H + (size_t)s0 * HID))[lane];
        ax = fmaf(v0.x, n0, ax); ay = fmaf(v0.y, n0, ay);
        az = fmaf(v0.z, n0, az); aw = fmaf(v0.w, n0, aw);
    }

    ax = fmaxf(ax, 0.f); ay = fmaxf(ay, 0.f);
    az = fmaxf(az, 0.f); aw = fmaxf(aw, 0.f);
    unsigned short h[4], l[4];
    split_bf16(ax, h[0], l[0]); split_bf16(ay, h[1], l[1]);
    split_bf16(az, h[2], l[2]); split_bf16(aw, h[3], l[3]);
    size_t o = (size_t)warp * HID + lane * 4;
    *(uint2*)(g_hhi + o) = make_uint2(h[0] | ((uint32_t)h[1] << 16), h[2] | ((uint32_t)h[3] << 16));
    *(uint2*)(g_hlo + o) = make_uint2(l[0] | ((uint32_t)l[1] << 16), l[2] | ((uint32_t)l[3] << 16));
}

__global__ __launch_bounds__(256) void k_prop_csr_out(
    const float* __restrict__ H,
    const float* __restrict__ bmu,
    const float* __restrict__ blv,
    float* __restrict__ out)
{
    int warp = (blockIdx.x * blockDim.x + threadIdx.x) >> 5;
    if (warp >= NN) return;
    int lane = threadIdx.x & 31;

    float di = g_dinv[warp];
    float s = di * di;
    float4 bb;
    float* dstp;
    if (lane < 16) {
        bb = ((const float4*)bmu)[lane];
        dstp = out + (size_t)warp * 64 + lane * 4;
    } else {
        bb = ((const float4*)blv)[lane - 16];
        dstp = out + (size_t)NN * 64 + (size_t)warp * 64 + (lane - 16) * 4;
    }
    float4 v = ((const float4*)(H + (size_t)warp * HID))[lane];
    float ax = fmaf(v.x, s, bb.x);
    float ay = fmaf(v.y, s, bb.y);
    float az = fmaf(v.z, s, bb.z);
    float aw = fmaf(v.w, s, bb.w);

    int e = g_off[warp];
    const int end = g_off[warp + 1];
    for (; e + 1 < end; e += 2) {
        int s0 = g_es[e],     s1 = g_es[e + 1];
        float n0 = g_en[e],   n1 = g_en[e + 1];
        float4 v0 = ((const float4*)(H + (size_t)s0 * HID))[lane];
        float4 v1 = ((const float4*)(H + (size_t)s1 * HID))[lane];
        ax = fmaf(v0.x, n0, ax); ay = fmaf(v0.y, n0, ay);
        az = fmaf(v0.z, n0, az); aw = fmaf(v0.w, n0, aw);
        ax = fmaf(v1.x, n1, ax); ay = fmaf(v1.y, n1, ay);
        az = fmaf(v1.z, n1, az); aw = fmaf(v1.w, n1, aw);
    }
    if (e < end) {
        int s0 = g_es[e];
        float n0 = g_en[e];
        float4 v0 = ((const float4*)(H + (size_t)s0 * HID))[lane];
        ax = fmaf(v0.x, n0, ax); ay = fmaf(v0.y, n0, ay);
        az = fmaf(v0.z, n0, az); aw = fmaf(v0.w, n0, aw);
    }

    *(float4*)dstp = make_float4(ax, ay, az, aw);
}

// ---------------------------------------------------------------------------
extern "C" void kernel_launch(void* const* d_in, const int* in_sizes, int n_in,
                              void* d_out, int out_size)
{
    const float* x   = (const float*)d_in[0];
    const int*   ei  = (const int*)d_in[1];
    const float* W1  = (const float*)d_in[2];
    const float* b1  = (const float*)d_in[3];
    const float* Wmu = (const float*)d_in[4];
    const float* bmu = (const float*)d_in[5];
    const float* Wlv = (const float*)d_in[6];
    const float* blv = (const float*)d_in[7];
    float* out = (float*)d_out;

    const int* src = ei;
    const int* dst = ei + NE;

    float *h_ptr;
    cudaGetSymbolAddress((void**)&h_ptr, g_h);
    __nv_bfloat16 *xhi, *xlo, *hhi, *hlo, *w1hi, *w1lo, *w2hi, *w2lo;
    cudaGetSymbolAddress((void**)&xhi, g_xhi);
    cudaGetSymbolAddress((void**)&xlo, g_xlo);
    cudaGetSymbolAddress((void**)&hhi, g_hhi);
    cudaGetSymbolAddress((void**)&hlo, g_hlo);
    cudaGetSymbolAddress((void**)&w1hi, g_w1hi);
    cudaGetSymbolAddress((void**)&w1lo, g_w1lo);
    cudaGetSymbolAddress((void**)&w2hi, g_w2hi);
    cudaGetSymbolAddress((void**)&w2lo, g_w2lo);

    cudaFuncSetAttribute(tgemm_bf16<INC>, cudaFuncAttributeMaxDynamicSharedMemorySize, SMEM_GEMM);
    cudaFuncSetAttribute(tgemm_bf16<HID>, cudaFuncAttributeMaxDynamicSharedMemorySize, SMEM_GEMM);

    const int TB = 256;

    // --- CSR build ---
    k_cnt_zero<<<(NN + TB - 1) / TB, TB>>>();
    k_count<<<(NE + TB - 1) / TB, TB>>>(dst);
    k_dinv<<<(NN + TB - 1) / TB, TB>>>();
    k_blocksum<<<NB, 1024>>>();
    k_bscan<<<1, 128>>>();
    k_offsets<<<NB, 1024>>>();
    k_scatter<<<(NE + TB - 1) / TB, TB>>>(src, dst);

    // --- Pre-conversions ---
    k_convx<<<(NN * (INC / 4) + TB - 1) / TB, TB>>>(x);
    k_convw1<<<(INC * HID + TB - 1) / TB, TB>>>(W1);
    k_convw2<<<(HID * HID + TB - 1) / TB, TB>>>(Wmu, Wlv);

    // --- Layer 1: h1 = x @ W1 ---
    tgemm_bf16<INC><<<(NN + 127) / 128, 256, SMEM_GEMM>>>(xhi, xlo, w1hi, w1lo, h_ptr, NN);

    // --- Propagate + ReLU + split ---
    k_prop_csr_split<<<(NN * 32 + TB - 1) / TB, TB>>>(h_ptr, b1);

    // --- Layer 2: h2 = relu(p) @ [W_mu | W_logvar] ---
    tgemm_bf16<HID><<<(NN + 127) / 128, 256, SMEM_GEMM>>>(hhi, hlo, w2hi, w2lo, h_ptr, NN);

    // --- Propagate to split output ---
    k_prop_csr_out<<<(NN * 32 + TB - 1) / TB, TB>>>(h_ptr, bmu, blv, out);
}

// round 8
// speedup vs baseline: 1.9044x; 1.1831x over previous
#include <cuda_runtime.h>
#include <cuda_bf16.h>
#include <cstdint>

#define NN 100000
#define NE 640000
#define INC 256
#define HID 128
#define NB  ((NN + 1023) / 1024)

// ---------------- scratch (__device__ globals) ----------------
__device__ float g_h[(size_t)NN * HID];
__device__ __nv_bfloat16 g_xhi[(size_t)NN * INC];
__device__ __nv_bfloat16 g_xlo[(size_t)NN * INC];
__device__ __nv_bfloat16 g_hhi[(size_t)NN * HID];
__device__ __nv_bfloat16 g_hlo[(size_t)NN * HID];
__device__ __nv_bfloat16 g_w1hi[INC * HID];      // [n=128][k=256]
__device__ __nv_bfloat16 g_w1lo[INC * HID];
__device__ __nv_bfloat16 g_w2hi[HID * HID];      // [n=128][k=128]
__device__ __nv_bfloat16 g_w2lo[HID * HID];
__device__ float g_dinv[NN];
__device__ int   g_cnt[NN];
__device__ int   g_off[NN + 1];
__device__ int   g_cursor[NN];
__device__ int   g_es[NE];
__device__ float g_en[NE];
__device__ int   g_bsum[128];

__device__ __forceinline__ void split_bf16(float x, unsigned short& hi, unsigned short& lo) {
    __nv_bfloat16 h = __float2bfloat16(x);
    float hf = __bfloat162float(h);
    __nv_bfloat16 l = __float2bfloat16(x - hf);
    hi = *reinterpret_cast<unsigned short*>(&h);
    lo = *reinterpret_cast<unsigned short*>(&l);
}

__device__ __forceinline__ uint32_t smem_u32(const void* p) {
    uint32_t a;
    asm("{ .reg .u64 t; cvta.to.shared.u64 t, %1; cvt.u32.u64 %0, t; }" : "=r"(a) : "l"(p));
    return a;
}

#define CP16(d, s) asm volatile("cp.async.cg.shared.global [%0], [%1], 16;" :: "r"(d), "l"(s) : "memory")
#define CPC()      asm volatile("cp.async.commit_group;" ::: "memory")
#define CPW(n)     asm volatile("cp.async.wait_group %0;" :: "n"(n) : "memory")

// ---------------------------------------------------------------------------
// Fused init: cnt_zero (blocks 0..390) + convW1 (391..518) + convW2 (519..582)
// ---------------------------------------------------------------------------
__global__ void k_init(const float* __restrict__ W1,
                       const float* __restrict__ Wmu,
                       const float* __restrict__ Wlv)
{
    int b = blockIdx.x;
    int t = threadIdx.x;
    if (b < 391) {
        int n = b * 256 + t;
        if (n < NN) g_cnt[n] = 0;
    } else if (b < 391 + 128) {
        int i = (b - 391) * 256 + t;        // i = n*256 + k, i < 32768
        int n = i >> 8, k = i & 255;
        unsigned short h, l;
        split_bf16(W1[k * 128 + n], h, l);
        g_w1hi[i] = *(__nv_bfloat16*)&h;
        g_w1lo[i] = *(__nv_bfloat16*)&l;
    } else {
        int i = (b - 519) * 256 + t;        // i = n*128 + k, i < 16384
        int n = i >> 7, k = i & 127;
        float v = (n < 64) ? Wmu[k * 64 + n] : Wlv[k * 64 + (n - 64)];
        unsigned short h, l;
        split_bf16(v, h, l);
        g_w2hi[i] = *(__nv_bfloat16*)&h;
        g_w2lo[i] = *(__nv_bfloat16*)&l;
    }
}

// ---------------------------------------------------------------------------
// Fused: degree count (blocks 0..2499) + convx (2500..27499)
// ---------------------------------------------------------------------------
__global__ void k_count_convx(const int* __restrict__ dst, const float* __restrict__ x)
{
    int b = blockIdx.x;
    int t = threadIdx.x;
    if (b < 2500) {
        int e = b * 256 + t;                // NE = 2500*256 exactly
        atomicAdd(&g_cnt[dst[e]], 1);
    } else {
        int i = (b - 2500) * 256 + t;       // NN*INC/4 = 25000*256 exactly
        float4 v = ((const float4*)x)[i];
        unsigned short h[4], l[4];
        split_bf16(v.x, h[0], l[0]); split_bf16(v.y, h[1], l[1]);
        split_bf16(v.z, h[2], l[2]); split_bf16(v.w, h[3], l[3]);
        ((uint2*)g_xhi)[i] = make_uint2(h[0] | ((uint32_t)h[1] << 16), h[2] | ((uint32_t)h[3] << 16));
        ((uint2*)g_xlo)[i] = make_uint2(l[0] | ((uint32_t)l[1] << 16), l[2] | ((uint32_t)l[3] << 16));
    }
}

// Phase 1 scan + dinv fused
__global__ __launch_bounds__(1024) void k_blocksum() {
    __shared__ int sm[1024];
    int i = blockIdx.x * 1024 + threadIdx.x;
    int v = (i < NN) ? g_cnt[i] : 0;
    if (i < NN) g_dinv[i] = rsqrtf(1.0f + (float)v);
    sm[threadIdx.x] = v;
    __syncthreads();
#pragma unroll
    for (int d = 512; d > 0; d >>= 1) {
        if (threadIdx.x < d) sm[threadIdx.x] += sm[threadIdx.x + d];
        __syncthreads();
    }
    if (threadIdx.x == 0) g_bsum[blockIdx.x] = sm[0];
}
__global__ void k_bscan() {
    __shared__ int sm[128];
    int t = threadIdx.x;
    int v = (t < NB) ? g_bsum[t] : 0;
    sm[t] = v;
    __syncthreads();
#pragma unroll
    for (int d = 1; d < 128; d <<= 1) {
        int x = (t >= d) ? sm[t - d] : 0;
        __syncthreads();
        sm[t] += x;
        __syncthreads();
    }
    if (t < 128) g_bsum[t] = sm[t] - v;
}
__global__ __launch_bounds__(1024) void k_offsets() {
    __shared__ int sm[1024];
    int i = blockIdx.x * 1024 + threadIdx.x;
    int v = (i < NN) ? g_cnt[i] : 0;
    sm[threadIdx.x] = v;
    __syncthreads();
#pragma unroll
    for (int d = 1; d < 1024; d <<= 1) {
        int x = (threadIdx.x >= d) ? sm[threadIdx.x - d] : 0;
        __syncthreads();
        sm[threadIdx.x] += x;
        __syncthreads();
    }
    if (i < NN) {
        int off = g_bsum[blockIdx.x] + sm[threadIdx.x] - v;
        g_off[i] = off;
        g_cursor[i] = off;
    }
    if (i == 0) g_off[NN] = NE;
}
__global__ void k_scatter(const int* __restrict__ src, const int* __restrict__ dst) {
    int e = blockIdx.x * blockDim.x + threadIdx.x;
    if (e >= NE) return;
    int s = src[e], d = dst[e];
    int pos = atomicAdd(&g_cursor[d], 1);
    g_es[pos] = s;
    g_en[pos] = g_dinv[s] * g_dinv[d];
}

// ---------------------------------------------------------------------------
// mma.sync bf16-split GEMM with cp.async double buffer + B-fragment caching.
// C[M,128] = A @ B^T; A planes [M][KT], B planes [128][KT].
// Block 256 thr, 8 warps (4M x 2N), block tile 128x128, chunk k=32, LDA=40.
// ---------------------------------------------------------------------------
#define MMA_BF16(c0,c1,c2,c3,a0,a1,a2,a3,b0,b1)                                  \
    asm volatile("mma.sync.aligned.m16n8k16.row.col.f32.bf16.bf16.f32 "          \
        "{%0,%1,%2,%3}, {%4,%5,%6,%7}, {%8,%9}, {%0,%1,%2,%3};"                  \
        : "+f"(c0), "+f"(c1), "+f"(c2), "+f"(c3)                                  \
        : "r"(a0), "r"(a1), "r"(a2), "r"(a3), "r"(b0), "r"(b1))

#define LDA   40                 // shorts per row (80 B, 16B-aligned, conflict-free)
#define PLANE 10240              // 128 rows * 80 B
#define BUFB  (4 * PLANE)        // AHI, ALO, BHI, BLO
#define SMEM_GEMM (2 * BUFB)     // 81920 B

template <int KT>
__global__ __launch_bounds__(256, 2) void tgemm_bf16(
    const __nv_bfloat16* __restrict__ Ahi, const __nv_bfloat16* __restrict__ Alo,
    const __nv_bfloat16* __restrict__ Bhi, const __nv_bfloat16* __restrict__ Blo,
    float* __restrict__ C, int M)
{
    extern __shared__ char sm[];
    const uint32_t smb = smem_u32(sm);

    const int t = threadIdx.x;
    const int w = t >> 5;
    const int lane = t & 31;
    const int g = lane >> 2;
    const int tg = lane & 3;
    const int warp_m = (w & 3) * 32;
    const int warp_n = (w >> 2) * 64;
    const int blockRow = blockIdx.x * 128;

    // staging: thread loads row lr, shorts [ko, ko+16)
    const int lr = t >> 1;
    const int ko = (t & 1) * 16;
    int grow = blockRow + lr;
    if (grow > M - 1) grow = M - 1;       // clamp; epilogue guards stores
    const __nv_bfloat16* apH = Ahi + (size_t)grow * KT + ko;
    const __nv_bfloat16* apL = Alo + (size_t)grow * KT + ko;
    const __nv_bfloat16* bpH = Bhi + (size_t)lr * KT + ko;
    const __nv_bfloat16* bpL = Blo + (size_t)lr * KT + ko;
    const uint32_t dstb = smb + lr * 80 + ko * 2;

    float acc[2][8][4];
#pragma unroll
    for (int i = 0; i < 2; i++)
#pragma unroll
        for (int j = 0; j < 8; j++)
#pragma unroll
            for (int k = 0; k < 4; k++) acc[i][j][k] = 0.0f;

    constexpr int NCHUNK = KT / 32;

    // prologue: issue chunk 0 into buffer 0
    {
        const uint32_t db = dstb;
        CP16(db + 0 * PLANE,      apH);  CP16(db + 0 * PLANE + 16, apH + 8);
        CP16(db + 1 * PLANE,      apL);  CP16(db + 1 * PLANE + 16, apL + 8);
        CP16(db + 2 * PLANE,      bpH);  CP16(db + 2 * PLANE + 16, bpH + 8);
        CP16(db + 3 * PLANE,      bpL);  CP16(db + 3 * PLANE + 16, bpL + 8);
        CPC();
    }

    int cur = 0;
#pragma unroll 1
    for (int c = 0; c < NCHUNK; c++) {
        if (c + 1 < NCHUNK) {
            const int kt = (c + 1) * 32;
            const uint32_t db = dstb + (cur ^ 1) * BUFB;
            CP16(db + 0 * PLANE,      apH + kt);  CP16(db + 0 * PLANE + 16, apH + kt + 8);
            CP16(db + 1 * PLANE,      apL + kt);  CP16(db + 1 * PLANE + 16, apL + kt + 8);
            CP16(db + 2 * PLANE,      bpH + kt);  CP16(db + 2 * PLANE + 16, bpH + kt + 8);
            CP16(db + 3 * PLANE,      bpL + kt);  CP16(db + 3 * PLANE + 16, bpL + kt + 8);
            CPC();
            CPW(1);
        } else {
            CPW(0);
        }
        __syncthreads();

        const unsigned short* sAhi = (const unsigned short*)(sm + (size_t)cur * BUFB + 0 * PLANE);
        const unsigned short* sAlo = (const unsigned short*)(sm + (size_t)cur * BUFB + 1 * PLANE);
        const unsigned short* sBhi = (const unsigned short*)(sm + (size_t)cur * BUFB + 2 * PLANE);
        const unsigned short* sBlo = (const unsigned short*)(sm + (size_t)cur * BUFB + 3 * PLANE);

#pragma unroll
        for (int ks = 0; ks < 2; ks++) {
            const int c0 = ks * 16 + 2 * tg;
            uint32_t ah[2][4], al[2][4];
#pragma unroll
            for (int mf = 0; mf < 2; mf++) {
                const int r0 = warp_m + mf * 16 + g;
                ah[mf][0] = *(const uint32_t*)&sAhi[(size_t)r0 * LDA + c0];
                ah[mf][1] = *(const uint32_t*)&sAhi[(size_t)(r0 + 8) * LDA + c0];
                ah[mf][2] = *(const uint32_t*)&sAhi[(size_t)r0 * LDA + c0 + 8];
                ah[mf][3] = *(const uint32_t*)&sAhi[(size_t)(r0 + 8) * LDA + c0 + 8];
                al[mf][0] = *(const uint32_t*)&sAlo[(size_t)r0 * LDA + c0];
                al[mf][1] = *(const uint32_t*)&sAlo[(size_t)(r0 + 8) * LDA + c0];
                al[mf][2] = *(const uint32_t*)&sAlo[(size_t)r0 * LDA + c0 + 8];
                al[mf][3] = *(const uint32_t*)&sAlo[(size_t)(r0 + 8) * LDA + c0 + 8];
            }
            // B fragments cached in registers, reused across all 3 passes
            uint32_t bh[8][2], bl[8][2];
#pragma unroll
            for (int nf = 0; nf < 8; nf++) {
                const int n = warp_n + nf * 8 + g;
                bh[nf][0] = *(const uint32_t*)&sBhi[(size_t)n * LDA + c0];
                bh[nf][1] = *(const uint32_t*)&sBhi[(size_t)n * LDA + c0 + 8];
                bl[nf][0] = *(const uint32_t*)&sBlo[(size_t)n * LDA + c0];
                bl[nf][1] = *(const uint32_t*)&sBlo[(size_t)n * LDA + c0 + 8];
            }
            // pass 0: ah x bh
#pragma unroll
            for (int nf = 0; nf < 8; nf++) {
                MMA_BF16(acc[0][nf][0], acc[0][nf][1], acc[0][nf][2], acc[0][nf][3],
                         ah[0][0], ah[0][1], ah[0][2], ah[0][3], bh[nf][0], bh[nf][1]);
                MMA_BF16(acc[1][nf][0], acc[1][nf][1], acc[1][nf][2], acc[1][nf][3],
                         ah[1][0], ah[1][1], ah[1][2], ah[1][3], bh[nf][0], bh[nf][1]);
            }
            // pass 1: ah x bl
#pragma unroll
            for (int nf = 0; nf < 8; nf++) {
                MMA_BF16(acc[0][nf][0], acc[0][nf][1], acc[0][nf][2], acc[0][nf][3],
                         ah[0][0], ah[0][1], ah[0][2], ah[0][3], bl[nf][0], bl[nf][1]);
                MMA_BF16(acc[1][nf][0], acc[1][nf][1], acc[1][nf][2], acc[1][nf][3],
                         ah[1][0], ah[1][1], ah[1][2], ah[1][3], bl[nf][0], bl[nf][1]);
            }
            // pass 2: al x bh
#pragma unroll
            for (int nf = 0; nf < 8; nf++) {
                MMA_BF16(acc[0][nf][0], acc[0][nf][1], acc[0][nf][2], acc[0][nf][3],
                         al[0][0], al[0][1], al[0][2], al[0][3], bh[nf][0], bh[nf][1]);
                MMA_BF16(acc[1][nf][0], acc[1][nf][1], acc[1][nf][2], acc[1][nf][3],
                         al[1][0], al[1][1], al[1][2], al[1][3], bh[nf][0], bh[nf][1]);
            }
        }
        __syncthreads();
        cur ^= 1;
    }

    // ---- epilogue ----
#pragma unroll
    for (int mf = 0; mf < 2; mf++) {
#pragma unroll
        for (int nf = 0; nf < 8; nf++) {
            const int row0 = blockRow + warp_m + mf * 16 + g;
            const int col = warp_n + nf * 8 + 2 * tg;
            if (row0 < M) {
                *(float2*)(C + (size_t)row0 * 128 + col) =
                    make_float2(acc[mf][nf][0], acc[mf][nf][1]);
            }
            if (row0 + 8 < M) {
                *(float2*)(C + (size_t)(row0 + 8) * 128 + col) =
                    make_float2(acc[mf][nf][2], acc[mf][nf][3]);
            }
        }
    }
}

// ---------------------------------------------------------------------------
// CSR propagation kernels
// ---------------------------------------------------------------------------
__global__ __launch_bounds__(256) void k_prop_csr_split(
    const float* __restrict__ H,
    const float* __restrict__ b)
{
    int warp = (blockIdx.x * blockDim.x + threadIdx.x) >> 5;
    if (warp >= NN) return;
    int lane = threadIdx.x & 31;

    float di = g_dinv[warp];
    float s = di * di;
    float4 bb = ((const float4*)b)[lane];
    float4 v = ((const float4*)(H + (size_t)warp * HID))[lane];
    float ax = fmaf(v.x, s, bb.x);
    float ay = fmaf(v.y, s, bb.y);
    float az = fmaf(v.z, s, bb.z);
    float aw = fmaf(v.w, s, bb.w);

    int e = g_off[warp];
    const int end = g_off[warp + 1];
    for (; e + 1 < end; e += 2) {
        int s0 = g_es[e],     s1 = g_es[e + 1];
        float n0 = g_en[e],   n1 = g_en[e + 1];
        float4 v0 = ((const float4*)(H + (size_t)s0 * HID))[lane];
        float4 v1 = ((const float4*)(H + (size_t)s1 * HID))[lane];
        ax = fmaf(v0.x, n0, ax); ay = fmaf(v0.y, n0, ay);
        az = fmaf(v0.z, n0, az); aw = fmaf(v0.w, n0, aw);
        ax = fmaf(v1.x, n1, ax); ay = fmaf(v1.y, n1, ay);
        az = fmaf(v1.z, n1, az); aw = fmaf(v1.w, n1, aw);
    }
    if (e < end) {
        int s0 = g_es[e];
        float n0 = g_en[e];
        float4 v0 = ((const float4*)(H + (size_t)s0 * HID))[lane];
        ax = fmaf(v0.x, n0, ax); ay = fmaf(v0.y, n0, ay);
        az = fmaf(v0.z, n0, az); aw = fmaf(v0.w, n0, aw);
    }

    ax = fmaxf(ax, 0.f); ay = fmaxf(ay, 0.f);
    az = fmaxf(az, 0.f); aw = fmaxf(aw, 0.f);
    unsigned short h[4], l[4];
    split_bf16(ax, h[0], l[0]); split_bf16(ay, h[1], l[1]);
    split_bf16(az, h[2], l[2]); split_bf16(aw, h[3], l[3]);
    size_t o = (size_t)warp * HID + lane * 4;
    *(uint2*)(g_hhi + o) = make_uint2(h[0] | ((uint32_t)h[1] << 16), h[2] | ((uint32_t)h[3] << 16));
    *(uint2*)(g_hlo + o) = make_uint2(l[0] | ((uint32_t)l[1] << 16), l[2] | ((uint32_t)l[3] << 16));
}

__global__ __launch_bounds__(256) void k_prop_csr_out(
    const float* __restrict__ H,
    const float* __restrict__ bmu,
    const float* __restrict__ blv,
    float* __restrict__ out)
{
    int warp = (blockIdx.x * blockDim.x + threadIdx.x) >> 5;
    if (warp >= NN) return;
    int lane = threadIdx.x & 31;

    float di = g_dinv[warp];
    float s = di * di;
    float4 bb;
    float* dstp;
    if (lane < 16) {
        bb = ((const float4*)bmu)[lane];
        dstp = out + (size_t)warp * 64 + lane * 4;
    } else {
        bb = ((const float4*)blv)[lane - 16];
        dstp = out + (size_t)NN * 64 + (size_t)warp * 64 + (lane - 16) * 4;
    }
    float4 v = ((const float4*)(H + (size_t)warp * HID))[lane];
    float ax = fmaf(v.x, s, bb.x);
    float ay = fmaf(v.y, s, bb.y);
    float az = fmaf(v.z, s, bb.z);
    float aw = fmaf(v.w, s, bb.w);

    int e = g_off[warp];
    const int end = g_off[warp + 1];
    for (; e + 1 < end; e += 2) {
        int s0 = g_es[e],     s1 = g_es[e + 1];
        float n0 = g_en[e],   n1 = g_en[e + 1];
        float4 v0 = ((const float4*)(H + (size_t)s0 * HID))[lane];
        float4 v1 = ((const float4*)(H + (size_t)s1 * HID))[lane];
        ax = fmaf(v0.x, n0, ax); ay = fmaf(v0.y, n0, ay);
        az = fmaf(v0.z, n0, az); aw = fmaf(v0.w, n0, aw);
        ax = fmaf(v1.x, n1, ax); ay = fmaf(v1.y, n1, ay);
        az = fmaf(v1.z, n1, az); aw = fmaf(v1.w, n1, aw);
    }
    if (e < end) {
        int s0 = g_es[e];
        float n0 = g_en[e];
        float4 v0 = ((const float4*)(H + (size_t)s0 * HID))[lane];
        ax = fmaf(v0.x, n0, ax); ay = fmaf(v0.y, n0, ay);
        az = fmaf(v0.z, n0, az); aw = fmaf(v0.w, n0, aw);
    }

    *(float4*)dstp = make_float4(ax, ay, az, aw);
}

// ---------------------------------------------------------------------------
extern "C" void kernel_launch(void* const* d_in, const int* in_sizes, int n_in,
                              void* d_out, int out_size)
{
    const float* x   = (const float*)d_in[0];
    const int*   ei  = (const int*)d_in[1];
    const float* W1  = (const float*)d_in[2];
    const float* b1  = (const float*)d_in[3];
    const float* Wmu = (const float*)d_in[4];
    const float* bmu = (const float*)d_in[5];
    const float* Wlv = (const float*)d_in[6];
    const float* blv = (const float*)d_in[7];
    float* out = (float*)d_out;

    const int* src = ei;
    const int* dst = ei + NE;

    float *h_ptr;
    cudaGetSymbolAddress((void**)&h_ptr, g_h);
    __nv_bfloat16 *xhi, *xlo, *hhi, *hlo, *w1hi, *w1lo, *w2hi, *w2lo;
    cudaGetSymbolAddress((void**)&xhi, g_xhi);
    cudaGetSymbolAddress((void**)&xlo, g_xlo);
    cudaGetSymbolAddress((void**)&hhi, g_hhi);
    cudaGetSymbolAddress((void**)&hlo, g_hlo);
    cudaGetSymbolAddress((void**)&w1hi, g_w1hi);
    cudaGetSymbolAddress((void**)&w1lo, g_w1lo);
    cudaGetSymbolAddress((void**)&w2hi, g_w2hi);
    cudaGetSymbolAddress((void**)&w2lo, g_w2lo);

    cudaFuncSetAttribute(tgemm_bf16<INC>, cudaFuncAttributeMaxDynamicSharedMemorySize, SMEM_GEMM);
    cudaFuncSetAttribute(tgemm_bf16<HID>, cudaFuncAttributeMaxDynamicSharedMemorySize, SMEM_GEMM);

    const int TB = 256;

    // --- init: cnt_zero + weight conversions (fused) ---
    k_init<<<583, TB>>>(W1, Wmu, Wlv);

    // --- degree count + x conversion (fused) ---
    k_count_convx<<<2500 + 25000, TB>>>(dst, x);

    // --- scan (+dinv fused into blocksum) ---
    k_blocksum<<<NB, 1024>>>();
    k_bscan<<<1, 128>>>();
    k_offsets<<<NB, 1024>>>();
    k_scatter<<<(NE + TB - 1) / TB, TB>>>(src, dst);

    // --- Layer 1: h1 = x @ W1 ---
    tgemm_bf16<INC><<<(NN + 127) / 128, 256, SMEM_GEMM>>>(xhi, xlo, w1hi, w1lo, h_ptr, NN);

    // --- Propagate + ReLU + split ---
    k_prop_csr_split<<<(NN * 32 + TB - 1) / TB, TB>>>(h_ptr, b1);

    // --- Layer 2: h2 = relu(p) @ [W_mu | W_logvar] ---
    tgemm_bf16<HID><<<(NN + 127) / 128, 256, SMEM_GEMM>>>(hhi, hlo, w2hi, w2lo, h_ptr, NN);

    // --- Propagate to split output ---
    k_prop_csr_out<<<(NN * 32 + TB - 1) / TB, TB>>>(h_ptr, bmu, blv, out);
}

// round 9
// speedup vs baseline: 2.0251x; 1.0634x over previous
#include <cuda_runtime.h>
#include <cuda_bf16.h>
#include <cstdint>

#define NN 100000
#define NE 640000
#define INC 256
#define HID 128
#define NB  ((NN + 1023) / 1024)

// ---------------- scratch (__device__ globals) ----------------
__device__ float g_h[(size_t)NN * HID];
__device__ __nv_bfloat16 g_hhi[(size_t)NN * HID];
__device__ __nv_bfloat16 g_hlo[(size_t)NN * HID];
__device__ __nv_bfloat16 g_w1hi[INC * HID];      // [n=128][k=256]
__device__ __nv_bfloat16 g_w1lo[INC * HID];
__device__ __nv_bfloat16 g_w2hi[HID * HID];      // [n=128][k=128]
__device__ __nv_bfloat16 g_w2lo[HID * HID];
__device__ float g_dinv[NN];
__device__ int   g_cnt[NN];
__device__ int   g_off[NN + 1];
__device__ int   g_cursor[NN];
__device__ int   g_es[NE];
__device__ float g_en[NE];
__device__ int   g_bsum[128];

__device__ __forceinline__ void split_bf16(float x, unsigned short& hi, unsigned short& lo) {
    __nv_bfloat16 h = __float2bfloat16(x);
    float hf = __bfloat162float(h);
    __nv_bfloat16 l = __float2bfloat16(x - hf);
    hi = *reinterpret_cast<unsigned short*>(&h);
    lo = *reinterpret_cast<unsigned short*>(&l);
}

// in-register truncation split of a float2 -> packed bf16x2 hi & lo words
__device__ __forceinline__ void cvt_pair(float2 v, uint32_t& hi, uint32_t& lo) {
    uint32_t x0 = __float_as_uint(v.x), x1 = __float_as_uint(v.y);
    hi = __byte_perm(x0, x1, 0x7632);                  // {x1.hi16, x0.hi16}
    float l0 = v.x - __uint_as_float(x0 & 0xffff0000u);
    float l1 = v.y - __uint_as_float(x1 & 0xffff0000u);
    asm("cvt.rn.bf16x2.f32 %0, %1, %2;" : "=r"(lo) : "f"(l1), "f"(l0));
}

__device__ __forceinline__ uint32_t smem_u32(const void* p) {
    uint32_t a;
    asm("{ .reg .u64 t; cvta.to.shared.u64 t, %1; cvt.u32.u64 %0, t; }" : "=r"(a) : "l"(p));
    return a;
}

#define CP16(d, s) asm volatile("cp.async.cg.shared.global [%0], [%1], 16;" :: "r"(d), "l"(s) : "memory")
#define CPC()      asm volatile("cp.async.commit_group;" ::: "memory")
#define CPW(n)     asm volatile("cp.async.wait_group %0;" :: "n"(n) : "memory")

#define MMA_BF16(c0,c1,c2,c3,a0,a1,a2,a3,b0,b1)                                  \
    asm volatile("mma.sync.aligned.m16n8k16.row.col.f32.bf16.bf16.f32 "          \
        "{%0,%1,%2,%3}, {%4,%5,%6,%7}, {%8,%9}, {%0,%1,%2,%3};"                  \
        : "+f"(c0), "+f"(c1), "+f"(c2), "+f"(c3)                                  \
        : "r"(a0), "r"(a1), "r"(a2), "r"(a3), "r"(b0), "r"(b1))

// ---------------------------------------------------------------------------
// Fused init: cnt_zero (blocks 0..390) + convW1 (391..518) + convW2 (519..582)
// ---------------------------------------------------------------------------
__global__ void k_init(const float* __restrict__ W1,
                       const float* __restrict__ Wmu,
                       const float* __restrict__ Wlv)
{
    int b = blockIdx.x;
    int t = threadIdx.x;
    if (b < 391) {
        int n = b * 256 + t;
        if (n < NN) g_cnt[n] = 0;
    } else if (b < 391 + 128) {
        int i = (b - 391) * 256 + t;        // i = n*256 + k
        int n = i >> 8, k = i & 255;
        unsigned short h, l;
        split_bf16(W1[k * 128 + n], h, l);
        g_w1hi[i] = *(__nv_bfloat16*)&h;
        g_w1lo[i] = *(__nv_bfloat16*)&l;
    } else {
        int i = (b - 519) * 256 + t;        // i = n*128 + k
        int n = i >> 7, k = i & 127;
        float v = (n < 64) ? Wmu[k * 64 + n] : Wlv[k * 64 + (n - 64)];
        unsigned short h, l;
        split_bf16(v, h, l);
        g_w2hi[i] = *(__nv_bfloat16*)&h;
        g_w2lo[i] = *(__nv_bfloat16*)&l;
    }
}

__global__ void k_count(const int* __restrict__ dst) {
    int e = blockIdx.x * blockDim.x + threadIdx.x;
    if (e < NE) atomicAdd(&g_cnt[dst[e]], 1);
}

__global__ __launch_bounds__(1024) void k_blocksum() {
    __shared__ int sm[1024];
    int i = blockIdx.x * 1024 + threadIdx.x;
    int v = (i < NN) ? g_cnt[i] : 0;
    if (i < NN) g_dinv[i] = rsqrtf(1.0f + (float)v);
    sm[threadIdx.x] = v;
    __syncthreads();
#pragma unroll
    for (int d = 512; d > 0; d >>= 1) {
        if (threadIdx.x < d) sm[threadIdx.x] += sm[threadIdx.x + d];
        __syncthreads();
    }
    if (threadIdx.x == 0) g_bsum[blockIdx.x] = sm[0];
}
__global__ void k_bscan() {
    __shared__ int sm[128];
    int t = threadIdx.x;
    int v = (t < NB) ? g_bsum[t] : 0;
    sm[t] = v;
    __syncthreads();
#pragma unroll
    for (int d = 1; d < 128; d <<= 1) {
        int x = (t >= d) ? sm[t - d] : 0;
        __syncthreads();
        sm[t] += x;
        __syncthreads();
    }
    if (t < 128) g_bsum[t] = sm[t] - v;
}
__global__ __launch_bounds__(1024) void k_offsets() {
    __shared__ int sm[1024];
    int i = blockIdx.x * 1024 + threadIdx.x;
    int v = (i < NN) ? g_cnt[i] : 0;
    sm[threadIdx.x] = v;
    __syncthreads();
#pragma unroll
    for (int d = 1; d < 1024; d <<= 1) {
        int x = (threadIdx.x >= d) ? sm[threadIdx.x - d] : 0;
        __syncthreads();
        sm[threadIdx.x] += x;
        __syncthreads();
    }
    if (i < NN) {
        int off = g_bsum[blockIdx.x] + sm[threadIdx.x] - v;
        g_off[i] = off;
        g_cursor[i] = off;
    }
    if (i == 0) g_off[NN] = NE;
}
__global__ void k_scatter(const int* __restrict__ src, const int* __restrict__ dst) {
    int e = blockIdx.x * blockDim.x + threadIdx.x;
    if (e >= NE) return;
    int s = src[e], d = dst[e];
    int pos = atomicAdd(&g_cursor[d], 1);
    g_es[pos] = s;
    g_en[pos] = g_dinv[s] * g_dinv[d];
}

// ---------------------------------------------------------------------------
// GEMM1: C[M,128] = x @ W^T, A = raw fp32 (in-register truncation split),
// B = preconverted bf16 hi/lo planes [128 n][KT]. cp.async double buffer.
// Block 256 thr, 8 warps (4M x 2N), tile 128x128, chunk k=32.
// ---------------------------------------------------------------------------
#define LDAF  36                     // fp32 words per A row (144 B, 16B-aligned)
#define APLANE (128 * LDAF * 4)      // 18432 B
#define LDB   40                     // bf16 shorts per B row (80 B)
#define BPLANE (128 * LDB * 2)       // 10240 B
#define FBUF  (APLANE + 2 * BPLANE)  // 38912 B
#define SMEM_F (2 * FBUF)            // 77824 B

__global__ __launch_bounds__(256, 2) void tgemm_f32a(
    const float* __restrict__ A,
    const __nv_bfloat16* __restrict__ Bhi, const __nv_bfloat16* __restrict__ Blo,
    float* __restrict__ C, int M)
{
    extern __shared__ char sm[];
    const uint32_t smb = smem_u32(sm);
    constexpr int KT = INC;

    const int t = threadIdx.x;
    const int w = t >> 5;
    const int lane = t & 31;
    const int g = lane >> 2;
    const int tg = lane & 3;
    const int warp_m = (w & 3) * 32;
    const int warp_n = (w >> 2) * 64;
    const int blockRow = blockIdx.x * 128;

    // staging: thread handles row lr; A: 16 floats at ko*? ; B: 16 shorts
    const int lr = t >> 1;
    const int koA = (t & 1) * 16;     // float offset within 32-float chunk row
    const int koB = (t & 1) * 16;     // short offset within 32-short chunk row
    int grow = blockRow + lr;
    if (grow > M - 1) grow = M - 1;
    const float* ap = A + (size_t)grow * KT + koA;
    const __nv_bfloat16* bpH = Bhi + (size_t)lr * KT + koB;
    const __nv_bfloat16* bpL = Blo + (size_t)lr * KT + koB;
    const uint32_t dstA = smb + lr * (LDAF * 4) + koA * 4;
    const uint32_t dstB = smb + APLANE + lr * (LDB * 2) + koB * 2;

    float acc[2][8][4];
#pragma unroll
    for (int i = 0; i < 2; i++)
#pragma unroll
        for (int j = 0; j < 8; j++)
#pragma unroll
            for (int k = 0; k < 4; k++) acc[i][j][k] = 0.0f;

    constexpr int NCHUNK = KT / 32;

    // prologue: chunk 0 -> buffer 0
    CP16(dstA,      ap);      CP16(dstA + 16, ap + 4);
    CP16(dstA + 32, ap + 8);  CP16(dstA + 48, ap + 12);
    CP16(dstB,              bpH);  CP16(dstB + 16,          bpH + 8);
    CP16(dstB + BPLANE,     bpL);  CP16(dstB + BPLANE + 16, bpL + 8);
    CPC();

    int cur = 0;
#pragma unroll 1
    for (int c = 0; c < NCHUNK; c++) {
        if (c + 1 < NCHUNK) {
            const int kt = (c + 1) * 32;
            const uint32_t dA = dstA + (cur ^ 1) * FBUF;
            const uint32_t dB = dstB + (cur ^ 1) * FBUF;
            CP16(dA,      ap + kt);      CP16(dA + 16, ap + kt + 4);
            CP16(dA + 32, ap + kt + 8);  CP16(dA + 48, ap + kt + 12);
            CP16(dB,              bpH + kt);  CP16(dB + 16,          bpH + kt + 8);
            CP16(dB + BPLANE,     bpL + kt);  CP16(dB + BPLANE + 16, bpL + kt + 8);
            CPC();
            CPW(1);
        } else {
            CPW(0);
        }
        __syncthreads();

        const float* sA = (const float*)(sm + (size_t)cur * FBUF);
        const unsigned short* sBhi = (const unsigned short*)(sm + (size_t)cur * FBUF + APLANE);
        const unsigned short* sBlo = (const unsigned short*)(sm + (size_t)cur * FBUF + APLANE + BPLANE);

#pragma unroll
        for (int ks = 0; ks < 2; ks++) {
            const int c0 = ks * 16 + 2 * tg;
            uint32_t ah[2][4], al[2][4];
#pragma unroll
            for (int mf = 0; mf < 2; mf++) {
                const int r0 = warp_m + mf * 16 + g;
                float2 v0 = *(const float2*)&sA[(size_t)r0 * LDAF + c0];
                float2 v1 = *(const float2*)&sA[(size_t)(r0 + 8) * LDAF + c0];
                float2 v2 = *(const float2*)&sA[(size_t)r0 * LDAF + c0 + 8];
                float2 v3 = *(const float2*)&sA[(size_t)(r0 + 8) * LDAF + c0 + 8];
                cvt_pair(v0, ah[mf][0], al[mf][0]);
                cvt_pair(v1, ah[mf][1], al[mf][1]);
                cvt_pair(v2, ah[mf][2], al[mf][2]);
                cvt_pair(v3, ah[mf][3], al[mf][3]);
            }
            uint32_t bh[8][2], bl[8][2];
#pragma unroll
            for (int nf = 0; nf < 8; nf++) {
                const int n = warp_n + nf * 8 + g;
                bh[nf][0] = *(const uint32_t*)&sBhi[(size_t)n * LDB + c0];
                bh[nf][1] = *(const uint32_t*)&sBhi[(size_t)n * LDB + c0 + 8];
                bl[nf][0] = *(const uint32_t*)&sBlo[(size_t)n * LDB + c0];
                bl[nf][1] = *(const uint32_t*)&sBlo[(size_t)n * LDB + c0 + 8];
            }
#pragma unroll
            for (int nf = 0; nf < 8; nf++) {
                MMA_BF16(acc[0][nf][0], acc[0][nf][1], acc[0][nf][2], acc[0][nf][3],
                         ah[0][0], ah[0][1], ah[0][2], ah[0][3], bh[nf][0], bh[nf][1]);
                MMA_BF16(acc[1][nf][0], acc[1][nf][1], acc[1][nf][2], acc[1][nf][3],
                         ah[1][0], ah[1][1], ah[1][2], ah[1][3], bh[nf][0], bh[nf][1]);
            }
#pragma unroll
            for (int nf = 0; nf < 8; nf++) {
                MMA_BF16(acc[0][nf][0], acc[0][nf][1], acc[0][nf][2], acc[0][nf][3],
                         ah[0][0], ah[0][1], ah[0][2], ah[0][3], bl[nf][0], bl[nf][1]);
                MMA_BF16(acc[1][nf][0], acc[1][nf][1], acc[1][nf][2], acc[1][nf][3],
                         ah[1][0], ah[1][1], ah[1][2], ah[1][3], bl[nf][0], bl[nf][1]);
            }
#pragma unroll
            for (int nf = 0; nf < 8; nf++) {
                MMA_BF16(acc[0][nf][0], acc[0][nf][1], acc[0][nf][2], acc[0][nf][3],
                         al[0][0], al[0][1], al[0][2], al[0][3], bh[nf][0], bh[nf][1]);
                MMA_BF16(acc[1][nf][0], acc[1][nf][1], acc[1][nf][2], acc[1][nf][3],
                         al[1][0], al[1][1], al[1][2], al[1][3], bh[nf][0], bh[nf][1]);
            }
        }
        __syncthreads();
        cur ^= 1;
    }

#pragma unroll
    for (int mf = 0; mf < 2; mf++) {
#pragma unroll
        for (int nf = 0; nf < 8; nf++) {
            const int row0 = blockRow + warp_m + mf * 16 + g;
            const int col = warp_n + nf * 8 + 2 * tg;
            if (row0 < M)
                *(float2*)(C + (size_t)row0 * 128 + col) =
                    make_float2(acc[mf][nf][0], acc[mf][nf][1]);
            if (row0 + 8 < M)
                *(float2*)(C + (size_t)(row0 + 8) * 128 + col) =
                    make_float2(acc[mf][nf][2], acc[mf][nf][3]);
        }
    }
}

// ---------------------------------------------------------------------------
// GEMM2: bf16-plane A (from prop1) — unchanged R8 kernel, KT=128.
// ---------------------------------------------------------------------------
#define LDA   40
#define PLANE 10240
#define BUFB  (4 * PLANE)
#define SMEM_GEMM (2 * BUFB)

__global__ __launch_bounds__(256, 2) void tgemm_bf16(
    const __nv_bfloat16* __restrict__ Ahi, const __nv_bfloat16* __restrict__ Alo,
    const __nv_bfloat16* __restrict__ Bhi, const __nv_bfloat16* __restrict__ Blo,
    float* __restrict__ C, int M)
{
    extern __shared__ char sm[];
    const uint32_t smb = smem_u32(sm);
    constexpr int KT = HID;

    const int t = threadIdx.x;
    const int w = t >> 5;
    const int lane = t & 31;
    const int g = lane >> 2;
    const int tg = lane & 3;
    const int warp_m = (w & 3) * 32;
    const int warp_n = (w >> 2) * 64;
    const int blockRow = blockIdx.x * 128;

    const int lr = t >> 1;
    const int ko = (t & 1) * 16;
    int grow = blockRow + lr;
    if (grow > M - 1) grow = M - 1;
    const __nv_bfloat16* apH = Ahi + (size_t)grow * KT + ko;
    const __nv_bfloat16* apL = Alo + (size_t)grow * KT + ko;
    const __nv_bfloat16* bpH = Bhi + (size_t)lr * KT + ko;
    const __nv_bfloat16* bpL = Blo + (size_t)lr * KT + ko;
    const uint32_t dstb = smb + lr * 80 + ko * 2;

    float acc[2][8][4];
#pragma unroll
    for (int i = 0; i < 2; i++)
#pragma unroll
        for (int j = 0; j < 8; j++)
#pragma unroll
            for (int k = 0; k < 4; k++) acc[i][j][k] = 0.0f;

    constexpr int NCHUNK = KT / 32;

    {
        const uint32_t db = dstb;
        CP16(db + 0 * PLANE, apH);  CP16(db + 0 * PLANE + 16, apH + 8);
        CP16(db + 1 * PLANE, apL);  CP16(db + 1 * PLANE + 16, apL + 8);
        CP16(db + 2 * PLANE, bpH);  CP16(db + 2 * PLANE + 16, bpH + 8);
        CP16(db + 3 * PLANE, bpL);  CP16(db + 3 * PLANE + 16, bpL + 8);
        CPC();
    }

    int cur = 0;
#pragma unroll 1
    for (int c = 0; c < NCHUNK; c++) {
        if (c + 1 < NCHUNK) {
            const int kt = (c + 1) * 32;
            const uint32_t db = dstb + (cur ^ 1) * BUFB;
            CP16(db + 0 * PLANE, apH + kt);  CP16(db + 0 * PLANE + 16, apH + kt + 8);
            CP16(db + 1 * PLANE, apL + kt);  CP16(db + 1 * PLANE + 16, apL + kt + 8);
            CP16(db + 2 * PLANE, bpH + kt);  CP16(db + 2 * PLANE + 16, bpH + kt + 8);
            CP16(db + 3 * PLANE, bpL + kt);  CP16(db + 3 * PLANE + 16, bpL + kt + 8);
            CPC();
            CPW(1);
        } else {
            CPW(0);
        }
        __syncthreads();

        const unsigned short* sAhi = (const unsigned short*)(sm + (size_t)cur * BUFB + 0 * PLANE);
        const unsigned short* sAlo = (const unsigned short*)(sm + (size_t)cur * BUFB + 1 * PLANE);
        const unsigned short* sBhi = (const unsigned short*)(sm + (size_t)cur * BUFB + 2 * PLANE);
        const unsigned short* sBlo = (const unsigned short*)(sm + (size_t)cur * BUFB + 3 * PLANE);

#pragma unroll
        for (int ks = 0; ks < 2; ks++) {
            const int c0 = ks * 16 + 2 * tg;
            uint32_t ah[2][4], al[2][4];
#pragma unroll
            for (int mf = 0; mf < 2; mf++) {
                const int r0 = warp_m + mf * 16 + g;
                ah[mf][0] = *(const uint32_t*)&sAhi[(size_t)r0 * LDA + c0];
                ah[mf][1] = *(const uint32_t*)&sAhi[(size_t)(r0 + 8) * LDA + c0];
                ah[mf][2] = *(const uint32_t*)&sAhi[(size_t)r0 * LDA + c0 + 8];
                ah[mf][3] = *(const uint32_t*)&sAhi[(size_t)(r0 + 8) * LDA + c0 + 8];
                al[mf][0] = *(const uint32_t*)&sAlo[(size_t)r0 * LDA + c0];
                al[mf][1] = *(const uint32_t*)&sAlo[(size_t)(r0 + 8) * LDA + c0];
                al[mf][2] = *(const uint32_t*)&sAlo[(size_t)r0 * LDA + c0 + 8];
                al[mf][3] = *(const uint32_t*)&sAlo[(size_t)(r0 + 8) * LDA + c0 + 8];
            }
            uint32_t bh[8][2], bl[8][2];
#pragma unroll
            for (int nf = 0; nf < 8; nf++) {
                const int n = warp_n + nf * 8 + g;
                bh[nf][0] = *(const uint32_t*)&sBhi[(size_t)n * LDA + c0];
                bh[nf][1] = *(const uint32_t*)&sBhi[(size_t)n * LDA + c0 + 8];
                bl[nf][0] = *(const uint32_t*)&sBlo[(size_t)n * LDA + c0];
                bl[nf][1] = *(const uint32_t*)&sBlo[(size_t)n * LDA + c0 + 8];
            }
#pragma unroll
            for (int nf = 0; nf < 8; nf++) {
                MMA_BF16(acc[0][nf][0], acc[0][nf][1], acc[0][nf][2], acc[0][nf][3],
                         ah[0][0], ah[0][1], ah[0][2], ah[0][3], bh[nf][0], bh[nf][1]);
                MMA_BF16(acc[1][nf][0], acc[1][nf][1], acc[1][nf][2], acc[1][nf][3],
                         ah[1][0], ah[1][1], ah[1][2], ah[1][3], bh[nf][0], bh[nf][1]);
            }
#pragma unroll
            for (int nf = 0; nf < 8; nf++) {
                MMA_BF16(acc[0][nf][0], acc[0][nf][1], acc[0][nf][2], acc[0][nf][3],
                         ah[0][0], ah[0][1], ah[0][2], ah[0][3], bl[nf][0], bl[nf][1]);
                MMA_BF16(acc[1][nf][0], acc[1][nf][1], acc[1][nf][2], acc[1][nf][3],
                         ah[1][0], ah[1][1], ah[1][2], ah[1][3], bl[nf][0], bl[nf][1]);
            }
#pragma unroll
            for (int nf = 0; nf < 8; nf++) {
                MMA_BF16(acc[0][nf][0], acc[0][nf][1], acc[0][nf][2], acc[0][nf][3],
                         al[0][0], al[0][1], al[0][2], al[0][3], bh[nf][0], bh[nf][1]);
                MMA_BF16(acc[1][nf][0], acc[1][nf][1], acc[1][nf][2], acc[1][nf][3],
                         al[1][0], al[1][1], al[1][2], al[1][3], bh[nf][0], bh[nf][1]);
            }
        }
        __syncthreads();
        cur ^= 1;
    }

#pragma unroll
    for (int mf = 0; mf < 2; mf++) {
#pragma unroll
        for (int nf = 0; nf < 8; nf++) {
            const int row0 = blockRow + warp_m + mf * 16 + g;
            const int col = warp_n + nf * 8 + 2 * tg;
            if (row0 < M)
                *(float2*)(C + (size_t)row0 * 128 + col) =
                    make_float2(acc[mf][nf][0], acc[mf][nf][1]);
            if (row0 + 8 < M)
                *(float2*)(C + (size_t)(row0 + 8) * 128 + col) =
                    make_float2(acc[mf][nf][2], acc[mf][nf][3]);
        }
    }
}

// ---------------------------------------------------------------------------
// CSR propagation, 4-way MLP unroll
// ---------------------------------------------------------------------------
#define PROP_BODY(GATHER_FMA_TAIL)                                              \
    int e = g_off[warp];                                                         \
    const int end = g_off[warp + 1];                                             \
    for (; e + 4 <= end; e += 4) {                                               \
        int s0 = g_es[e], s1 = g_es[e + 1], s2 = g_es[e + 2], s3 = g_es[e + 3];  \
        float m0 = g_en[e], m1 = g_en[e + 1], m2 = g_en[e + 2], m3 = g_en[e + 3];\
        float4 v0 = ((const float4*)(H + (size_t)s0 * HID))[lane];               \
        float4 v1 = ((const float4*)(H + (size_t)s1 * HID))[lane];               \
        float4 v2 = ((const float4*)(H + (size_t)s2 * HID))[lane];               \
        float4 v3 = ((const float4*)(H + (size_t)s3 * HID))[lane];               \
        ax = fmaf(v0.x, m0, ax); ay = fmaf(v0.y, m0, ay);                        \
        az = fmaf(v0.z, m0, az); aw = fmaf(v0.w, m0, aw);                        \
        ax = fmaf(v1.x, m1, ax); ay = fmaf(v1.y, m1, ay);                        \
        az = fmaf(v1.z, m1, az); aw = fmaf(v1.w, m1, aw);                        \
        ax = fmaf(v2.x, m2, ax); ay = fmaf(v2.y, m2, ay);                        \
        az = fmaf(v2.z, m2, az); aw = fmaf(v2.w, m2, aw);                        \
        ax = fmaf(v3.x, m3, ax); ay = fmaf(v3.y, m3, ay);                        \
        az = fmaf(v3.z, m3, az); aw = fmaf(v3.w, m3, aw);                        \
    }                                                                            \
    for (; e < end; e++) {                                                       \
        int s0 = g_es[e];                                                        \
        float m0 = g_en[e];                                                      \
        float4 v0 = ((const float4*)(H + (size_t)s0 * HID))[lane];               \
        ax = fmaf(v0.x, m0, ax); ay = fmaf(v0.y, m0, ay);                        \
        az = fmaf(v0.z, m0, az); aw = fmaf(v0.w, m0, aw);                        \
    }

__global__ __launch_bounds__(256) void k_prop_csr_split(
    const float* __restrict__ H,
    const float* __restrict__ b)
{
    int warp = (blockIdx.x * blockDim.x + threadIdx.x) >> 5;
    if (warp >= NN) return;
    int lane = threadIdx.x & 31;

    float di = g_dinv[warp];
    float s = di * di;
    float4 bb = ((const float4*)b)[lane];
    float4 v = ((const float4*)(H + (size_t)warp * HID))[lane];
    float ax = fmaf(v.x, s, bb.x);
    float ay = fmaf(v.y, s, bb.y);
    float az = fmaf(v.z, s, bb.z);
    float aw = fmaf(v.w, s, bb.w);

    PROP_BODY()

    ax = fmaxf(ax, 0.f); ay = fmaxf(ay, 0.f);
    az = fmaxf(az, 0.f); aw = fmaxf(aw, 0.f);
    unsigned short h[4], l[4];
    split_bf16(ax, h[0], l[0]); split_bf16(ay, h[1], l[1]);
    split_bf16(az, h[2], l[2]); split_bf16(aw, h[3], l[3]);
    size_t o = (size_t)warp * HID + lane * 4;
    *(uint2*)(g_hhi + o) = make_uint2(h[0] | ((uint32_t)h[1] << 16), h[2] | ((uint32_t)h[3] << 16));
    *(uint2*)(g_hlo + o) = make_uint2(l[0] | ((uint32_t)l[1] << 16), l[2] | ((uint32_t)l[3] << 16));
}

__global__ __launch_bounds__(256) void k_prop_csr_out(
    const float* __restrict__ H,
    const float* __restrict__ bmu,
    const float* __restrict__ blv,
    float* __restrict__ out)
{
    int warp = (blockIdx.x * blockDim.x + threadIdx.x) >> 5;
    if (warp >= NN) return;
    int lane = threadIdx.x & 31;

    float di = g_dinv[warp];
    float s = di * di;
    float4 bb;
    float* dstp;
    if (lane < 16) {
        bb = ((const float4*)bmu)[lane];
        dstp = out + (size_t)warp * 64 + lane * 4;
    } else {
        bb = ((const float4*)blv)[lane - 16];
        dstp = out + (size_t)NN * 64 + (size_t)warp * 64 + (lane - 16) * 4;
    }
    float4 v = ((const float4*)(H + (size_t)warp * HID))[lane];
    float ax = fmaf(v.x, s, bb.x);
    float ay = fmaf(v.y, s, bb.y);
    float az = fmaf(v.z, s, bb.z);
    float aw = fmaf(v.w, s, bb.w);

    PROP_BODY()

    *(float4*)dstp = make_float4(ax, ay, az, aw);
}

// ---------------------------------------------------------------------------
extern "C" void kernel_launch(void* const* d_in, const int* in_sizes, int n_in,
                              void* d_out, int out_size)
{
    const float* x   = (const float*)d_in[0];
    const int*   ei  = (const int*)d_in[1];
    const float* W1  = (const float*)d_in[2];
    const float* b1  = (const float*)d_in[3];
    const float* Wmu = (const float*)d_in[4];
    const float* bmu = (const float*)d_in[5];
    const float* Wlv = (const float*)d_in[6];
    const float* blv = (const float*)d_in[7];
    float* out = (float*)d_out;

    const int* src = ei;
    const int* dst = ei + NE;

    float *h_ptr;
    cudaGetSymbolAddress((void**)&h_ptr, g_h);
    __nv_bfloat16 *hhi, *hlo, *w1hi, *w1lo, *w2hi, *w2lo;
    cudaGetSymbolAddress((void**)&hhi, g_hhi);
    cudaGetSymbolAddress((void**)&hlo, g_hlo);
    cudaGetSymbolAddress((void**)&w1hi, g_w1hi);
    cudaGetSymbolAddress((void**)&w1lo, g_w1lo);
    cudaGetSymbolAddress((void**)&w2hi, g_w2hi);
    cudaGetSymbolAddress((void**)&w2lo, g_w2lo);

    cudaFuncSetAttribute(tgemm_f32a, cudaFuncAttributeMaxDynamicSharedMemorySize, SMEM_F);
    cudaFuncSetAttribute(tgemm_bf16, cudaFuncAttributeMaxDynamicSharedMemorySize, SMEM_GEMM);

    const int TB = 256;

    // --- init: cnt_zero + weight conversions (fused) ---
    k_init<<<583, TB>>>(W1, Wmu, Wlv);

    // --- degree count ---
    k_count<<<(NE + TB - 1) / TB, TB>>>(dst);

    // --- scan (+dinv) + scatter ---
    k_blocksum<<<NB, 1024>>>();
    k_bscan<<<1, 128>>>();
    k_offsets<<<NB, 1024>>>();
    k_scatter<<<(NE + TB - 1) / TB, TB>>>(src, dst);

    // --- Layer 1: h1 = x @ W1 (fp32 A, in-register split) ---
    tgemm_f32a<<<(NN + 127) / 128, 256, SMEM_F>>>(x, w1hi, w1lo, h_ptr, NN);

    // --- Propagate + ReLU + split ---
    k_prop_csr_split<<<(NN * 32 + TB - 1) / TB, TB>>>(h_ptr, b1);

    // --- Layer 2: h2 = relu(p) @ [W_mu | W_logvar] ---
    tgemm_bf16<<<(NN + 127) / 128, 256, SMEM_GEMM>>>(hhi, hlo, w2hi, w2lo, h_ptr, NN);

    // --- Propagate to split output ---
    k_prop_csr_out<<<(NN * 32 + TB - 1) / TB, TB>>>(h_ptr, bmu, blv, out);
}

// round 10
// speedup vs baseline: 2.0389x; 1.0068x over previous
#include <cuda_runtime.h>
#include <cuda_bf16.h>
#include <cstdint>

#define NN 100000
#define NE 640000
#define INC 256
#define HID 128
#define NB  ((NN + 1023) / 1024)

// ---------------- scratch (__device__ globals) ----------------
__device__ float g_h[(size_t)NN * HID];
__device__ __nv_bfloat16 g_hhi[(size_t)NN * HID];
__device__ __nv_bfloat16 g_hlo[(size_t)NN * HID];
__device__ __nv_bfloat16 g_w1hi[INC * HID];      // [n=128][k=256]
__device__ __nv_bfloat16 g_w1lo[INC * HID];
__device__ __nv_bfloat16 g_w2hi[HID * HID];      // [n=128][k=128]
__device__ __nv_bfloat16 g_w2lo[HID * HID];
__device__ float g_dinv[NN];
__device__ int   g_cnt[NN];          // BSS-zeroed at load; re-zeroed by k_alloc each call
__device__ int   g_off[NN];
__device__ int   g_end[NN];
__device__ int   g_cursor[NN];
__device__ int   g_es[NE];
__device__ float g_en[NE];
__device__ int   g_total;

__device__ __forceinline__ void split_bf16(float x, unsigned short& hi, unsigned short& lo) {
    __nv_bfloat16 h = __float2bfloat16(x);
    float hf = __bfloat162float(h);
    __nv_bfloat16 l = __float2bfloat16(x - hf);
    hi = *reinterpret_cast<unsigned short*>(&h);
    lo = *reinterpret_cast<unsigned short*>(&l);
}

// in-register truncation split of a float2 -> packed bf16x2 hi & lo words
__device__ __forceinline__ void cvt_pair(float2 v, uint32_t& hi, uint32_t& lo) {
    uint32_t x0 = __float_as_uint(v.x), x1 = __float_as_uint(v.y);
    hi = __byte_perm(x0, x1, 0x7632);
    float l0 = v.x - __uint_as_float(x0 & 0xffff0000u);
    float l1 = v.y - __uint_as_float(x1 & 0xffff0000u);
    asm("cvt.rn.bf16x2.f32 %0, %1, %2;" : "=r"(lo) : "f"(l1), "f"(l0));
}

__device__ __forceinline__ uint32_t smem_u32(const void* p) {
    uint32_t a;
    asm("{ .reg .u64 t; cvta.to.shared.u64 t, %1; cvt.u32.u64 %0, t; }" : "=r"(a) : "l"(p));
    return a;
}

#define CP16(d, s) asm volatile("cp.async.cg.shared.global [%0], [%1], 16;" :: "r"(d), "l"(s) : "memory")
#define CPC()      asm volatile("cp.async.commit_group;" ::: "memory")
#define CPW(n)     asm volatile("cp.async.wait_group %0;" :: "n"(n) : "memory")

#define MMA_BF16(c0,c1,c2,c3,a0,a1,a2,a3,b0,b1)                                  \
    asm volatile("mma.sync.aligned.m16n8k16.row.col.f32.bf16.bf16.f32 "          \
        "{%0,%1,%2,%3}, {%4,%5,%6,%7}, {%8,%9}, {%0,%1,%2,%3};"                  \
        : "+f"(c0), "+f"(c1), "+f"(c2), "+f"(c3)                                  \
        : "r"(a0), "r"(a1), "r"(a2), "r"(a3), "r"(b0), "r"(b1))

// ---------------------------------------------------------------------------
// Fused: degree count (blocks 0..2499) + convW1 (2500..2627) + convW2
// (2628..2691) + g_total reset. g_cnt is guaranteed zero on entry (BSS at
// load; k_alloc re-zeroes after consuming).
// ---------------------------------------------------------------------------
__global__ void k_count_init(const int* __restrict__ dst,
                             const float* __restrict__ W1,
                             const float* __restrict__ Wmu,
                             const float* __restrict__ Wlv)
{
    int b = blockIdx.x;
    int t = threadIdx.x;
    if (b == 0 && t == 0) g_total = 0;
    if (b < 2500) {
        int e = b * 256 + t;                 // NE = 2500*256 exactly
        atomicAdd(&g_cnt[dst[e]], 1);
    } else if (b < 2500 + 128) {
        int i = (b - 2500) * 256 + t;        // i = n*256 + k
        int n = i >> 8, k = i & 255;
        unsigned short h, l;
        split_bf16(W1[k * 128 + n], h, l);
        g_w1hi[i] = *(__nv_bfloat16*)&h;
        g_w1lo[i] = *(__nv_bfloat16*)&l;
    } else {
        int i = (b - 2628) * 256 + t;        // i = n*128 + k
        int n = i >> 7, k = i & 127;
        float v = (n < 64) ? Wmu[k * 64 + n] : Wlv[k * 64 + (n - 64)];
        unsigned short h, l;
        split_bf16(v, h, l);
        g_w2hi[i] = *(__nv_bfloat16*)&h;
        g_w2lo[i] = *(__nv_bfloat16*)&l;
    }
}

// ---------------------------------------------------------------------------
// Single-kernel segment allocation: block-local scan + atomic base grab.
// Segments are disjoint (arrival-ordered); props use g_off/g_end pairs.
// Also computes dinv and re-zeroes g_cnt for the next call.
// ---------------------------------------------------------------------------
__global__ __launch_bounds__(1024) void k_alloc() {
    __shared__ int sm[1024];
    __shared__ int base;
    const int t = threadIdx.x;
    const int i = blockIdx.x * 1024 + t;
    int v = 0;
    if (i < NN) {
        v = g_cnt[i];
        g_cnt[i] = 0;                           // leave zeroed for next call
        g_dinv[i] = rsqrtf(1.0f + (float)v);
    }
    sm[t] = v;
    __syncthreads();
#pragma unroll
    for (int d = 1; d < 1024; d <<= 1) {
        int x = (t >= d) ? sm[t - d] : 0;
        __syncthreads();
        sm[t] += x;
        __syncthreads();
    }
    if (t == 1023) base = atomicAdd(&g_total, sm[1023]);
    __syncthreads();
    if (i < NN) {
        int off = base + sm[t] - v;             // exclusive within block + base
        g_off[i] = off;
        g_end[i] = off + v;
        g_cursor[i] = off;
    }
}

__global__ void k_scatter(const int* __restrict__ src, const int* __restrict__ dst) {
    int e = blockIdx.x * blockDim.x + threadIdx.x;
    if (e >= NE) return;
    int s = src[e], d = dst[e];
    int pos = atomicAdd(&g_cursor[d], 1);
    g_es[pos] = s;
    g_en[pos] = g_dinv[s] * g_dinv[d];
}

// ---------------------------------------------------------------------------
// GEMM1: C[M,128] = x @ W^T, A = raw fp32 (in-register truncation split),
// B = preconverted bf16 hi/lo planes. cp.async double buffer.
// ---------------------------------------------------------------------------
#define LDAF  36
#define APLANE (128 * LDAF * 4)
#define LDB   40
#define BPLANE (128 * LDB * 2)
#define FBUF  (APLANE + 2 * BPLANE)
#define SMEM_F (2 * FBUF)

__global__ __launch_bounds__(256, 2) void tgemm_f32a(
    const float* __restrict__ A,
    const __nv_bfloat16* __restrict__ Bhi, const __nv_bfloat16* __restrict__ Blo,
    float* __restrict__ C, int M)
{
    extern __shared__ char sm[];
    const uint32_t smb = smem_u32(sm);
    constexpr int KT = INC;

    const int t = threadIdx.x;
    const int w = t >> 5;
    const int lane = t & 31;
    const int g = lane >> 2;
    const int tg = lane & 3;
    const int warp_m = (w & 3) * 32;
    const int warp_n = (w >> 2) * 64;
    const int blockRow = blockIdx.x * 128;

    const int lr = t >> 1;
    const int koA = (t & 1) * 16;
    const int koB = (t & 1) * 16;
    int grow = blockRow + lr;
    if (grow > M - 1) grow = M - 1;
    const float* ap = A + (size_t)grow * KT + koA;
    const __nv_bfloat16* bpH = Bhi + (size_t)lr * KT + koB;
    const __nv_bfloat16* bpL = Blo + (size_t)lr * KT + koB;
    const uint32_t dstA = smb + lr * (LDAF * 4) + koA * 4;
    const uint32_t dstB = smb + APLANE + lr * (LDB * 2) + koB * 2;

    float acc[2][8][4];
#pragma unroll
    for (int i = 0; i < 2; i++)
#pragma unroll
        for (int j = 0; j < 8; j++)
#pragma unroll
            for (int k = 0; k < 4; k++) acc[i][j][k] = 0.0f;

    constexpr int NCHUNK = KT / 32;

    CP16(dstA,      ap);      CP16(dstA + 16, ap + 4);
    CP16(dstA + 32, ap + 8);  CP16(dstA + 48, ap + 12);
    CP16(dstB,              bpH);  CP16(dstB + 16,          bpH + 8);
    CP16(dstB + BPLANE,     bpL);  CP16(dstB + BPLANE + 16, bpL + 8);
    CPC();

    int cur = 0;
#pragma unroll 1
    for (int c = 0; c < NCHUNK; c++) {
        if (c + 1 < NCHUNK) {
            const int kt = (c + 1) * 32;
            const uint32_t dA = dstA + (cur ^ 1) * FBUF;
            const uint32_t dB = dstB + (cur ^ 1) * FBUF;
            CP16(dA,      ap + kt);      CP16(dA + 16, ap + kt + 4);
            CP16(dA + 32, ap + kt + 8);  CP16(dA + 48, ap + kt + 12);
            CP16(dB,              bpH + kt);  CP16(dB + 16,          bpH + kt + 8);
            CP16(dB + BPLANE,     bpL + kt);  CP16(dB + BPLANE + 16, bpL + kt + 8);
            CPC();
            CPW(1);
        } else {
            CPW(0);
        }
        __syncthreads();

        const float* sA = (const float*)(sm + (size_t)cur * FBUF);
        const unsigned short* sBhi = (const unsigned short*)(sm + (size_t)cur * FBUF + APLANE);
        const unsigned short* sBlo = (const unsigned short*)(sm + (size_t)cur * FBUF + APLANE + BPLANE);

#pragma unroll
        for (int ks = 0; ks < 2; ks++) {
            const int c0 = ks * 16 + 2 * tg;
            uint32_t ah[2][4], al[2][4];
#pragma unroll
            for (int mf = 0; mf < 2; mf++) {
                const int r0 = warp_m + mf * 16 + g;
                float2 v0 = *(const float2*)&sA[(size_t)r0 * LDAF + c0];
                float2 v1 = *(const float2*)&sA[(size_t)(r0 + 8) * LDAF + c0];
                float2 v2 = *(const float2*)&sA[(size_t)r0 * LDAF + c0 + 8];
                float2 v3 = *(const float2*)&sA[(size_t)(r0 + 8) * LDAF + c0 + 8];
                cvt_pair(v0, ah[mf][0], al[mf][0]);
                cvt_pair(v1, ah[mf][1], al[mf][1]);
                cvt_pair(v2, ah[mf][2], al[mf][2]);
                cvt_pair(v3, ah[mf][3], al[mf][3]);
            }
            uint32_t bh[8][2], bl[8][2];
#pragma unroll
            for (int nf = 0; nf < 8; nf++) {
                const int n = warp_n + nf * 8 + g;
                bh[nf][0] = *(const uint32_t*)&sBhi[(size_t)n * LDB + c0];
                bh[nf][1] = *(const uint32_t*)&sBhi[(size_t)n * LDB + c0 + 8];
                bl[nf][0] = *(const uint32_t*)&sBlo[(size_t)n * LDB + c0];
                bl[nf][1] = *(const uint32_t*)&sBlo[(size_t)n * LDB + c0 + 8];
            }
#pragma unroll
            for (int nf = 0; nf < 8; nf++) {
                MMA_BF16(acc[0][nf][0], acc[0][nf][1], acc[0][nf][2], acc[0][nf][3],
                         ah[0][0], ah[0][1], ah[0][2], ah[0][3], bh[nf][0], bh[nf][1]);
                MMA_BF16(acc[1][nf][0], acc[1][nf][1], acc[1][nf][2], acc[1][nf][3],
                         ah[1][0], ah[1][1], ah[1][2], ah[1][3], bh[nf][0], bh[nf][1]);
            }
#pragma unroll
            for (int nf = 0; nf < 8; nf++) {
                MMA_BF16(acc[0][nf][0], acc[0][nf][1], acc[0][nf][2], acc[0][nf][3],
                         ah[0][0], ah[0][1], ah[0][2], ah[0][3], bl[nf][0], bl[nf][1]);
                MMA_BF16(acc[1][nf][0], acc[1][nf][1], acc[1][nf][2], acc[1][nf][3],
                         ah[1][0], ah[1][1], ah[1][2], ah[1][3], bl[nf][0], bl[nf][1]);
            }
#pragma unroll
            for (int nf = 0; nf < 8; nf++) {
                MMA_BF16(acc[0][nf][0], acc[0][nf][1], acc[0][nf][2], acc[0][nf][3],
                         al[0][0], al[0][1], al[0][2], al[0][3], bh[nf][0], bh[nf][1]);
                MMA_BF16(acc[1][nf][0], acc[1][nf][1], acc[1][nf][2], acc[1][nf][3],
                         al[1][0], al[1][1], al[1][2], al[1][3], bh[nf][0], bh[nf][1]);
            }
        }
        __syncthreads();
        cur ^= 1;
    }

#pragma unroll
    for (int mf = 0; mf < 2; mf++) {
#pragma unroll
        for (int nf = 0; nf < 8; nf++) {
            const int row0 = blockRow + warp_m + mf * 16 + g;
            const int col = warp_n + nf * 8 + 2 * tg;
            if (row0 < M)
                *(float2*)(C + (size_t)row0 * 128 + col) =
                    make_float2(acc[mf][nf][0], acc[mf][nf][1]);
            if (row0 + 8 < M)
                *(float2*)(C + (size_t)(row0 + 8) * 128 + col) =
                    make_float2(acc[mf][nf][2], acc[mf][nf][3]);
        }
    }
}

// ---------------------------------------------------------------------------
// GEMM2: bf16-plane A (from prop1), KT=128.
// ---------------------------------------------------------------------------
#define LDA   40
#define PLANE 10240
#define BUFB  (4 * PLANE)
#define SMEM_GEMM (2 * BUFB)

__global__ __launch_bounds__(256, 2) void tgemm_bf16(
    const __nv_bfloat16* __restrict__ Ahi, const __nv_bfloat16* __restrict__ Alo,
    const __nv_bfloat16* __restrict__ Bhi, const __nv_bfloat16* __restrict__ Blo,
    float* __restrict__ C, int M)
{
    extern __shared__ char sm[];
    const uint32_t smb = smem_u32(sm);
    constexpr int KT = HID;

    const int t = threadIdx.x;
    const int w = t >> 5;
    const int lane = t & 31;
    const int g = lane >> 2;
    const int tg = lane & 3;
    const int warp_m = (w & 3) * 32;
    const int warp_n = (w >> 2) * 64;
    const int blockRow = blockIdx.x * 128;

    const int lr = t >> 1;
    const int ko = (t & 1) * 16;
    int grow = blockRow + lr;
    if (grow > M - 1) grow = M - 1;
    const __nv_bfloat16* apH = Ahi + (size_t)grow * KT + ko;
    const __nv_bfloat16* apL = Alo + (size_t)grow * KT + ko;
    const __nv_bfloat16* bpH = Bhi + (size_t)lr * KT + ko;
    const __nv_bfloat16* bpL = Blo + (size_t)lr * KT + ko;
    const uint32_t dstb = smb + lr * 80 + ko * 2;

    float acc[2][8][4];
#pragma unroll
    for (int i = 0; i < 2; i++)
#pragma unroll
        for (int j = 0; j < 8; j++)
#pragma unroll
            for (int k = 0; k < 4; k++) acc[i][j][k] = 0.0f;

    constexpr int NCHUNK = KT / 32;

    {
        const uint32_t db = dstb;
        CP16(db + 0 * PLANE, apH);  CP16(db + 0 * PLANE + 16, apH + 8);
        CP16(db + 1 * PLANE, apL);  CP16(db + 1 * PLANE + 16, apL + 8);
        CP16(db + 2 * PLANE, bpH);  CP16(db + 2 * PLANE + 16, bpH + 8);
        CP16(db + 3 * PLANE, bpL);  CP16(db + 3 * PLANE + 16, bpL + 8);
        CPC();
    }

    int cur = 0;
#pragma unroll 1
    for (int c = 0; c < NCHUNK; c++) {
        if (c + 1 < NCHUNK) {
            const int kt = (c + 1) * 32;
            const uint32_t db = dstb + (cur ^ 1) * BUFB;
            CP16(db + 0 * PLANE, apH + kt);  CP16(db + 0 * PLANE + 16, apH + kt + 8);
            CP16(db + 1 * PLANE, apL + kt);  CP16(db + 1 * PLANE + 16, apL + kt + 8);
            CP16(db + 2 * PLANE, bpH + kt);  CP16(db + 2 * PLANE + 16, bpH + kt + 8);
            CP16(db + 3 * PLANE, bpL + kt);  CP16(db + 3 * PLANE + 16, bpL + kt + 8);
            CPC();
            CPW(1);
        } else {
            CPW(0);
        }
        __syncthreads();

        const unsigned short* sAhi = (const unsigned short*)(sm + (size_t)cur * BUFB + 0 * PLANE);
        const unsigned short* sAlo = (const unsigned short*)(sm + (size_t)cur * BUFB + 1 * PLANE);
        const unsigned short* sBhi = (const unsigned short*)(sm + (size_t)cur * BUFB + 2 * PLANE);
        const unsigned short* sBlo = (const unsigned short*)(sm + (size_t)cur * BUFB + 3 * PLANE);

#pragma unroll
        for (int ks = 0; ks < 2; ks++) {
            const int c0 = ks * 16 + 2 * tg;
            uint32_t ah[2][4], al[2][4];
#pragma unroll
            for (int mf = 0; mf < 2; mf++) {
                const int r0 = warp_m + mf * 16 + g;
                ah[mf][0] = *(const uint32_t*)&sAhi[(size_t)r0 * LDA + c0];
                ah[mf][1] = *(const uint32_t*)&sAhi[(size_t)(r0 + 8) * LDA + c0];
                ah[mf][2] = *(const uint32_t*)&sAhi[(size_t)r0 * LDA + c0 + 8];
                ah[mf][3] = *(const uint32_t*)&sAhi[(size_t)(r0 + 8) * LDA + c0 + 8];
                al[mf][0] = *(const uint32_t*)&sAlo[(size_t)r0 * LDA + c0];
                al[mf][1] = *(const uint32_t*)&sAlo[(size_t)(r0 + 8) * LDA + c0];
                al[mf][2] = *(const uint32_t*)&sAlo[(size_t)r0 * LDA + c0 + 8];
                al[mf][3] = *(const uint32_t*)&sAlo[(size_t)(r0 + 8) * LDA + c0 + 8];
            }
            uint32_t bh[8][2], bl[8][2];
#pragma unroll
            for (int nf = 0; nf < 8; nf++) {
                const int n = warp_n + nf * 8 + g;
                bh[nf][0] = *(const uint32_t*)&sBhi[(size_t)n * LDA + c0];
                bh[nf][1] = *(const uint32_t*)&sBhi[(size_t)n * LDA + c0 + 8];
                bl[nf][0] = *(const uint32_t*)&sBlo[(size_t)n * LDA + c0];
                bl[nf][1] = *(const uint32_t*)&sBlo[(size_t)n * LDA + c0 + 8];
            }
#pragma unroll
            for (int nf = 0; nf < 8; nf++) {
                MMA_BF16(acc[0][nf][0], acc[0][nf][1], acc[0][nf][2], acc[0][nf][3],
                         ah[0][0], ah[0][1], ah[0][2], ah[0][3], bh[nf][0], bh[nf][1]);
                MMA_BF16(acc[1][nf][0], acc[1][nf][1], acc[1][nf][2], acc[1][nf][3],
                         ah[1][0], ah[1][1], ah[1][2], ah[1][3], bh[nf][0], bh[nf][1]);
            }
#pragma unroll
            for (int nf = 0; nf < 8; nf++) {
                MMA_BF16(acc[0][nf][0], acc[0][nf][1], acc[0][nf][2], acc[0][nf][3],
                         ah[0][0], ah[0][1], ah[0][2], ah[0][3], bl[nf][0], bl[nf][1]);
                MMA_BF16(acc[1][nf][0], acc[1][nf][1], acc[1][nf][2], acc[1][nf][3],
                         ah[1][0], ah[1][1], ah[1][2], ah[1][3], bl[nf][0], bl[nf][1]);
            }
#pragma unroll
            for (int nf = 0; nf < 8; nf++) {
                MMA_BF16(acc[0][nf][0], acc[0][nf][1], acc[0][nf][2], acc[0][nf][3],
                         al[0][0], al[0][1], al[0][2], al[0][3], bh[nf][0], bh[nf][1]);
                MMA_BF16(acc[1][nf][0], acc[1][nf][1], acc[1][nf][2], acc[1][nf][3],
                         al[1][0], al[1][1], al[1][2], al[1][3], bh[nf][0], bh[nf][1]);
            }
        }
        __syncthreads();
        cur ^= 1;
    }

#pragma unroll
    for (int mf = 0; mf < 2; mf++) {
#pragma unroll
        for (int nf = 0; nf < 8; nf++) {
            const int row0 = blockRow + warp_m + mf * 16 + g;
            const int col = warp_n + nf * 8 + 2 * tg;
            if (row0 < M)
                *(float2*)(C + (size_t)row0 * 128 + col) =
                    make_float2(acc[mf][nf][0], acc[mf][nf][1]);
            if (row0 + 8 < M)
                *(float2*)(C + (size_t)(row0 + 8) * 128 + col) =
                    make_float2(acc[mf][nf][2], acc[mf][nf][3]);
        }
    }
}

// ---------------------------------------------------------------------------
// CSR propagation, 4-way MLP unroll; segments via g_off/g_end
// ---------------------------------------------------------------------------
#define PROP_BODY()                                                              \
    int e = g_off[warp];                                                         \
    const int end = g_end[warp];                                                 \
    for (; e + 4 <= end; e += 4) {                                               \
        int s0 = g_es[e], s1 = g_es[e + 1], s2 = g_es[e + 2], s3 = g_es[e + 3];  \
        float m0 = g_en[e], m1 = g_en[e + 1], m2 = g_en[e + 2], m3 = g_en[e + 3];\
        float4 v0 = ((const float4*)(H + (size_t)s0 * HID))[lane];               \
        float4 v1 = ((const float4*)(H + (size_t)s1 * HID))[lane];               \
        float4 v2 = ((const float4*)(H + (size_t)s2 * HID))[lane];               \
        float4 v3 = ((const float4*)(H + (size_t)s3 * HID))[lane];               \
        ax = fmaf(v0.x, m0, ax); ay = fmaf(v0.y, m0, ay);                        \
        az = fmaf(v0.z, m0, az); aw = fmaf(v0.w, m0, aw);                        \
        ax = fmaf(v1.x, m1, ax); ay = fmaf(v1.y, m1, ay);                        \
        az = fmaf(v1.z, m1, az); aw = fmaf(v1.w, m1, aw);                        \
        ax = fmaf(v2.x, m2, ax); ay = fmaf(v2.y, m2, ay);                        \
        az = fmaf(v2.z, m2, az); aw = fmaf(v2.w, m2, aw);                        \
        ax = fmaf(v3.x, m3, ax); ay = fmaf(v3.y, m3, ay);                        \
        az = fmaf(v3.z, m3, az); aw = fmaf(v3.w, m3, aw);                        \
    }                                                                            \
    for (; e < end; e++) {                                                       \
        int s0 = g_es[e];                                                        \
        float m0 = g_en[e];                                                      \
        float4 v0 = ((const float4*)(H + (size_t)s0 * HID))[lane];               \
        ax = fmaf(v0.x, m0, ax); ay = fmaf(v0.y, m0, ay);                        \
        az = fmaf(v0.z, m0, az); aw = fmaf(v0.w, m0, aw);                        \
    }

__global__ __launch_bounds__(256) void k_prop_csr_split(
    const float* __restrict__ H,
    const float* __restrict__ b)
{
    int warp = (blockIdx.x * blockDim.x + threadIdx.x) >> 5;
    if (warp >= NN) return;
    int lane = threadIdx.x & 31;

    float di = g_dinv[warp];
    float s = di * di;
    float4 bb = ((const float4*)b)[lane];
    float4 v = ((const float4*)(H + (size_t)warp * HID))[lane];
    float ax = fmaf(v.x, s, bb.x);
    float ay = fmaf(v.y, s, bb.y);
    float az = fmaf(v.z, s, bb.z);
    float aw = fmaf(v.w, s, bb.w);

    PROP_BODY()

    ax = fmaxf(ax, 0.f); ay = fmaxf(ay, 0.f);
    az = fmaxf(az, 0.f); aw = fmaxf(aw, 0.f);
    unsigned short h[4], l[4];
    split_bf16(ax, h[0], l[0]); split_bf16(ay, h[1], l[1]);
    split_bf16(az, h[2], l[2]); split_bf16(aw, h[3], l[3]);
    size_t o = (size_t)warp * HID + lane * 4;
    *(uint2*)(g_hhi + o) = make_uint2(h[0] | ((uint32_t)h[1] << 16), h[2] | ((uint32_t)h[3] << 16));
    *(uint2*)(g_hlo + o) = make_uint2(l[0] | ((uint32_t)l[1] << 16), l[2] | ((uint32_t)l[3] << 16));
}

__global__ __launch_bounds__(256) void k_prop_csr_out(
    const float* __restrict__ H,
    const float* __restrict__ bmu,
    const float* __restrict__ blv,
    float* __restrict__ out)
{
    int warp = (blockIdx.x * blockDim.x + threadIdx.x) >> 5;
    if (warp >= NN) return;
    int lane = threadIdx.x & 31;

    float di = g_dinv[warp];
    float s = di * di;
    float4 bb;
    float* dstp;
    if (lane < 16) {
        bb = ((const float4*)bmu)[lane];
        dstp = out + (size_t)warp * 64 + lane * 4;
    } else {
        bb = ((const float4*)blv)[lane - 16];
        dstp = out + (size_t)NN * 64 + (size_t)warp * 64 + (lane - 16) * 4;
    }
    float4 v = ((const float4*)(H + (size_t)warp * HID))[lane];
    float ax = fmaf(v.x, s, bb.x);
    float ay = fmaf(v.y, s, bb.y);
    float az = fmaf(v.z, s, bb.z);
    float aw = fmaf(v.w, s, bb.w);

    PROP_BODY()

    *(float4*)dstp = make_float4(ax, ay, az, aw);
}

// ---------------------------------------------------------------------------
extern "C" void kernel_launch(void* const* d_in, const int* in_sizes, int n_in,
                              void* d_out, int out_size)
{
    const float* x   = (const float*)d_in[0];
    const int*   ei  = (const int*)d_in[1];
    const float* W1  = (const float*)d_in[2];
    const float* b1  = (const float*)d_in[3];
    const float* Wmu = (const float*)d_in[4];
    const float* bmu = (const float*)d_in[5];
    const float* Wlv = (const float*)d_in[6];
    const float* blv = (const float*)d_in[7];
    float* out = (float*)d_out;

    const int* src = ei;
    const int* dst = ei + NE;

    float *h_ptr;
    cudaGetSymbolAddress((void**)&h_ptr, g_h);
    __nv_bfloat16 *hhi, *hlo, *w1hi, *w1lo, *w2hi, *w2lo;
    cudaGetSymbolAddress((void**)&hhi, g_hhi);
    cudaGetSymbolAddress((void**)&hlo, g_hlo);
    cudaGetSymbolAddress((void**)&w1hi, g_w1hi);
    cudaGetSymbolAddress((void**)&w1lo, g_w1lo);
    cudaGetSymbolAddress((void**)&w2hi, g_w2hi);
    cudaGetSymbolAddress((void**)&w2lo, g_w2lo);

    cudaFuncSetAttribute(tgemm_f32a, cudaFuncAttributeMaxDynamicSharedMemorySize, SMEM_F);
    cudaFuncSetAttribute(tgemm_bf16, cudaFuncAttributeMaxDynamicSharedMemorySize, SMEM_GEMM);

    const int TB = 256;

    // --- CSR build (3 kernels) ---
    k_count_init<<<2692, TB>>>(dst, W1, Wmu, Wlv);
    k_alloc<<<NB, 1024>>>();
    k_scatter<<<(NE + TB - 1) / TB, TB>>>(src, dst);

    // --- Layer 1: h1 = x @ W1 (fp32 A, in-register split) ---
    tgemm_f32a<<<(NN + 127) / 128, 256, SMEM_F>>>(x, w1hi, w1lo, h_ptr, NN);

    // --- Propagate + ReLU + split ---
    k_prop_csr_split<<<(NN * 32 + TB - 1) / TB, TB>>>(h_ptr, b1);

    // --- Layer 2: h2 = relu(p) @ [W_mu | W_logvar] ---
    tgemm_bf16<<<(NN + 127) / 128, 256, SMEM_GEMM>>>(hhi, hlo, w2hi, w2lo, h_ptr, NN);

    // --- Propagate to split output ---
    k_prop_csr_out<<<(NN * 32 + TB - 1) / TB, TB>>>(h_ptr, bmu, blv, out);
}

// round 11
// speedup vs baseline: 2.1339x; 1.0466x over previous
#include <cuda_runtime.h>
#include <cuda_bf16.h>
#include <cstdint>

#define NN 100000
#define NE 640000
#define INC 256
#define HID 128
#define NB  ((NN + 1023) / 1024)

// ---------------- scratch (__device__ globals) ----------------
__device__ float g_h[(size_t)NN * HID];
__device__ __nv_bfloat16 g_hhi[(size_t)NN * HID];
__device__ __nv_bfloat16 g_hlo[(size_t)NN * HID];
__device__ __nv_bfloat16 g_w1hi[INC * HID];      // [n=128][k=256]
__device__ __nv_bfloat16 g_w1lo[INC * HID];
__device__ __nv_bfloat16 g_w2hi[HID * HID];      // [n=128][k=128]
__device__ __nv_bfloat16 g_w2lo[HID * HID];
__device__ float g_dinv[NN];
__device__ int   g_cnt[NN];          // zero on entry; re-zeroed by k_alloc
__device__ int   g_off[NN];
__device__ int   g_end[NN];
__device__ int   g_cursor[NN];
__device__ int   g_es[NE];
__device__ float g_en[NE];
__device__ int   g_total;

__device__ __forceinline__ void split_bf16(float x, unsigned short& hi, unsigned short& lo) {
    __nv_bfloat16 h = __float2bfloat16(x);
    float hf = __bfloat162float(h);
    __nv_bfloat16 l = __float2bfloat16(x - hf);
    hi = *reinterpret_cast<unsigned short*>(&h);
    lo = *reinterpret_cast<unsigned short*>(&l);
}

// in-register truncation split of a float2 -> packed bf16x2 hi & lo words
__device__ __forceinline__ void cvt_pair(float2 v, uint32_t& hi, uint32_t& lo) {
    uint32_t x0 = __float_as_uint(v.x), x1 = __float_as_uint(v.y);
    hi = __byte_perm(x0, x1, 0x7632);
    float l0 = v.x - __uint_as_float(x0 & 0xffff0000u);
    float l1 = v.y - __uint_as_float(x1 & 0xffff0000u);
    asm("cvt.rn.bf16x2.f32 %0, %1, %2;" : "=r"(lo) : "f"(l1), "f"(l0));
}

__device__ __forceinline__ uint32_t smem_u32(const void* p) {
    uint32_t a;
    asm("{ .reg .u64 t; cvta.to.shared.u64 t, %1; cvt.u32.u64 %0, t; }" : "=r"(a) : "l"(p));
    return a;
}

#define CP16(d, s) asm volatile("cp.async.cg.shared.global [%0], [%1], 16;" :: "r"(d), "l"(s) : "memory")
#define CPC()      asm volatile("cp.async.commit_group;" ::: "memory")
#define CPW(n)     asm volatile("cp.async.wait_group %0;" :: "n"(n) : "memory")

#define MMA_BF16(c0,c1,c2,c3,a0,a1,a2,a3,b0,b1)                                  \
    asm volatile("mma.sync.aligned.m16n8k16.row.col.f32.bf16.bf16.f32 "          \
        "{%0,%1,%2,%3}, {%4,%5,%6,%7}, {%8,%9}, {%0,%1,%2,%3};"                  \
        : "+f"(c0), "+f"(c1), "+f"(c2), "+f"(c3)                                  \
        : "r"(a0), "r"(a1), "r"(a2), "r"(a3), "r"(b0), "r"(b1))

// ---------------------------------------------------------------------------
// W1 conversion (must precede GEMM1, main stream)
// ---------------------------------------------------------------------------
__global__ void k_convw1(const float* __restrict__ W1) {
    int i = blockIdx.x * 256 + threadIdx.x;      // i = n*256 + k, 32768 total
    int n = i >> 8, k = i & 255;
    unsigned short h, l;
    split_bf16(W1[k * 128 + n], h, l);
    g_w1hi[i] = *(__nv_bfloat16*)&h;
    g_w1lo[i] = *(__nv_bfloat16*)&l;
}

// ---------------------------------------------------------------------------
// Side-stream: degree count (blocks 0..2499) + convW2 (2500..2563) + reset
// ---------------------------------------------------------------------------
__global__ void k_count_init(const int* __restrict__ dst,
                             const float* __restrict__ Wmu,
                             const float* __restrict__ Wlv)
{
    int b = blockIdx.x;
    int t = threadIdx.x;
    if (b == 0 && t == 0) g_total = 0;
    if (b < 2500) {
        int e = b * 256 + t;                 // NE = 2500*256 exactly
        atomicAdd(&g_cnt[dst[e]], 1);
    } else {
        int i = (b - 2500) * 256 + t;        // i = n*128 + k, 16384 total
        int n = i >> 7, k = i & 127;
        float v = (n < 64) ? Wmu[k * 64 + n] : Wlv[k * 64 + (n - 64)];
        unsigned short h, l;
        split_bf16(v, h, l);
        g_w2hi[i] = *(__nv_bfloat16*)&h;
        g_w2lo[i] = *(__nv_bfloat16*)&l;
    }
}

// ---------------------------------------------------------------------------
// Segment allocation: block-local scan + atomic base grab (+dinv, cnt reset)
// ---------------------------------------------------------------------------
__global__ __launch_bounds__(1024) void k_alloc() {
    __shared__ int sm[1024];
    __shared__ int base;
    const int t = threadIdx.x;
    const int i = blockIdx.x * 1024 + t;
    int v = 0;
    if (i < NN) {
        v = g_cnt[i];
        g_cnt[i] = 0;
        g_dinv[i] = rsqrtf(1.0f + (float)v);
    }
    sm[t] = v;
    __syncthreads();
#pragma unroll
    for (int d = 1; d < 1024; d <<= 1) {
        int x = (t >= d) ? sm[t - d] : 0;
        __syncthreads();
        sm[t] += x;
        __syncthreads();
    }
    if (t == 1023) base = atomicAdd(&g_total, sm[1023]);
    __syncthreads();
    if (i < NN) {
        int off = base + sm[t] - v;
        g_off[i] = off;
        g_end[i] = off + v;
        g_cursor[i] = off;
    }
}

__global__ void k_scatter(const int* __restrict__ src, const int* __restrict__ dst) {
    int e = blockIdx.x * blockDim.x + threadIdx.x;
    if (e >= NE) return;
    int s = src[e], d = dst[e];
    int pos = atomicAdd(&g_cursor[d], 1);
    g_es[pos] = s;
    g_en[pos] = g_dinv[s] * g_dinv[d];
}

// ---------------------------------------------------------------------------
// GEMM1: C[M,128] = x @ W^T, A = raw fp32 (in-register truncation split),
// B = preconverted bf16 hi/lo planes. cp.async double buffer.
// ---------------------------------------------------------------------------
#define LDAF  36
#define APLANE (128 * LDAF * 4)
#define LDB   40
#define BPLANE (128 * LDB * 2)
#define FBUF  (APLANE + 2 * BPLANE)
#define SMEM_F (2 * FBUF)

__global__ __launch_bounds__(256, 2) void tgemm_f32a(
    const float* __restrict__ A,
    const __nv_bfloat16* __restrict__ Bhi, const __nv_bfloat16* __restrict__ Blo,
    float* __restrict__ C, int M)
{
    extern __shared__ char sm[];
    const uint32_t smb = smem_u32(sm);
    constexpr int KT = INC;

    const int t = threadIdx.x;
    const int w = t >> 5;
    const int lane = t & 31;
    const int g = lane >> 2;
    const int tg = lane & 3;
    const int warp_m = (w & 3) * 32;
    const int warp_n = (w >> 2) * 64;
    const int blockRow = blockIdx.x * 128;

    const int lr = t >> 1;
    const int koA = (t & 1) * 16;
    const int koB = (t & 1) * 16;
    int grow = blockRow + lr;
    if (grow > M - 1) grow = M - 1;
    const float* ap = A + (size_t)grow * KT + koA;
    const __nv_bfloat16* bpH = Bhi + (size_t)lr * KT + koB;
    const __nv_bfloat16* bpL = Blo + (size_t)lr * KT + koB;
    const uint32_t dstA = smb + lr * (LDAF * 4) + koA * 4;
    const uint32_t dstB = smb + APLANE + lr * (LDB * 2) + koB * 2;

    float acc[2][8][4];
#pragma unroll
    for (int i = 0; i < 2; i++)
#pragma unroll
        for (int j = 0; j < 8; j++)
#pragma unroll
            for (int k = 0; k < 4; k++) acc[i][j][k] = 0.0f;

    constexpr int NCHUNK = KT / 32;

    CP16(dstA,      ap);      CP16(dstA + 16, ap + 4);
    CP16(dstA + 32, ap + 8);  CP16(dstA + 48, ap + 12);
    CP16(dstB,              bpH);  CP16(dstB + 16,          bpH + 8);
    CP16(dstB + BPLANE,     bpL);  CP16(dstB + BPLANE + 16, bpL + 8);
    CPC();

    int cur = 0;
#pragma unroll 1
    for (int c = 0; c < NCHUNK; c++) {
        if (c + 1 < NCHUNK) {
            const int kt = (c + 1) * 32;
            const uint32_t dA = dstA + (cur ^ 1) * FBUF;
            const uint32_t dB = dstB + (cur ^ 1) * FBUF;
            CP16(dA,      ap + kt);      CP16(dA + 16, ap + kt + 4);
            CP16(dA + 32, ap + kt + 8);  CP16(dA + 48, ap + kt + 12);
            CP16(dB,              bpH + kt);  CP16(dB + 16,          bpH + kt + 8);
            CP16(dB + BPLANE,     bpL + kt);  CP16(dB + BPLANE + 16, bpL + kt + 8);
            CPC();
            CPW(1);
        } else {
            CPW(0);
        }
        __syncthreads();

        const float* sA = (const float*)(sm + (size_t)cur * FBUF);
        const unsigned short* sBhi = (const unsigned short*)(sm + (size_t)cur * FBUF + APLANE);
        const unsigned short* sBlo = (const unsigned short*)(sm + (size_t)cur * FBUF + APLANE + BPLANE);

#pragma unroll
        for (int ks = 0; ks < 2; ks++) {
            const int c0 = ks * 16 + 2 * tg;
            uint32_t ah[2][4], al[2][4];
#pragma unroll
            for (int mf = 0; mf < 2; mf++) {
                const int r0 = warp_m + mf * 16 + g;
                float2 v0 = *(const float2*)&sA[(size_t)r0 * LDAF + c0];
                float2 v1 = *(const float2*)&sA[(size_t)(r0 + 8) * LDAF + c0];
                float2 v2 = *(const float2*)&sA[(size_t)r0 * LDAF + c0 + 8];
                float2 v3 = *(const float2*)&sA[(size_t)(r0 + 8) * LDAF + c0 + 8];
                cvt_pair(v0, ah[mf][0], al[mf][0]);
                cvt_pair(v1, ah[mf][1], al[mf][1]);
                cvt_pair(v2, ah[mf][2], al[mf][2]);
                cvt_pair(v3, ah[mf][3], al[mf][3]);
            }
            uint32_t bh[8][2], bl[8][2];
#pragma unroll
            for (int nf = 0; nf < 8; nf++) {
                const int n = warp_n + nf * 8 + g;
                bh[nf][0] = *(const uint32_t*)&sBhi[(size_t)n * LDB + c0];
                bh[nf][1] = *(const uint32_t*)&sBhi[(size_t)n * LDB + c0 + 8];
                bl[nf][0] = *(const uint32_t*)&sBlo[(size_t)n * LDB + c0];
                bl[nf][1] = *(const uint32_t*)&sBlo[(size_t)n * LDB + c0 + 8];
            }
#pragma unroll
            for (int nf = 0; nf < 8; nf++) {
                MMA_BF16(acc[0][nf][0], acc[0][nf][1], acc[0][nf][2], acc[0][nf][3],
                         ah[0][0], ah[0][1], ah[0][2], ah[0][3], bh[nf][0], bh[nf][1]);
                MMA_BF16(acc[1][nf][0], acc[1][nf][1], acc[1][nf][2], acc[1][nf][3],
                         ah[1][0], ah[1][1], ah[1][2], ah[1][3], bh[nf][0], bh[nf][1]);
            }
#pragma unroll
            for (int nf = 0; nf < 8; nf++) {
                MMA_BF16(acc[0][nf][0], acc[0][nf][1], acc[0][nf][2], acc[0][nf][3],
                         ah[0][0], ah[0][1], ah[0][2], ah[0][3], bl[nf][0], bl[nf][1]);
                MMA_BF16(acc[1][nf][0], acc[1][nf][1], acc[1][nf][2], acc[1][nf][3],
                         ah[1][0], ah[1][1], ah[1][2], ah[1][3], bl[nf][0], bl[nf][1]);
            }
#pragma unroll
            for (int nf = 0; nf < 8; nf++) {
                MMA_BF16(acc[0][nf][0], acc[0][nf][1], acc[0][nf][2], acc[0][nf][3],
                         al[0][0], al[0][1], al[0][2], al[0][3], bh[nf][0], bh[nf][1]);
                MMA_BF16(acc[1][nf][0], acc[1][nf][1], acc[1][nf][2], acc[1][nf][3],
                         al[1][0], al[1][1], al[1][2], al[1][3], bh[nf][0], bh[nf][1]);
            }
        }
        __syncthreads();
        cur ^= 1;
    }

#pragma unroll
    for (int mf = 0; mf < 2; mf++) {
#pragma unroll
        for (int nf = 0; nf < 8; nf++) {
            const int row0 = blockRow + warp_m + mf * 16 + g;
            const int col = warp_n + nf * 8 + 2 * tg;
            if (row0 < M)
                *(float2*)(C + (size_t)row0 * 128 + col) =
                    make_float2(acc[mf][nf][0], acc[mf][nf][1]);
            if (row0 + 8 < M)
                *(float2*)(C + (size_t)(row0 + 8) * 128 + col) =
                    make_float2(acc[mf][nf][2], acc[mf][nf][3]);
        }
    }
}

// ---------------------------------------------------------------------------
// GEMM2: bf16-plane A (from prop1), KT=128.
// ---------------------------------------------------------------------------
#define LDA   40
#define PLANE 10240
#define BUFB  (4 * PLANE)
#define SMEM_GEMM (2 * BUFB)

__global__ __launch_bounds__(256, 2) void tgemm_bf16(
    const __nv_bfloat16* __restrict__ Ahi, const __nv_bfloat16* __restrict__ Alo,
    const __nv_bfloat16* __restrict__ Bhi, const __nv_bfloat16* __restrict__ Blo,
    float* __restrict__ C, int M)
{
    extern __shared__ char sm[];
    const uint32_t smb = smem_u32(sm);
    constexpr int KT = HID;

    const int t = threadIdx.x;
    const int w = t >> 5;
    const int lane = t & 31;
    const int g = lane >> 2;
    const int tg = lane & 3;
    const int warp_m = (w & 3) * 32;
    const int warp_n = (w >> 2) * 64;
    const int blockRow = blockIdx.x * 128;

    const int lr = t >> 1;
    const int ko = (t & 1) * 16;
    int grow = blockRow + lr;
    if (grow > M - 1) grow = M - 1;
    const __nv_bfloat16* apH = Ahi + (size_t)grow * KT + ko;
    const __nv_bfloat16* apL = Alo + (size_t)grow * KT + ko;
    const __nv_bfloat16* bpH = Bhi + (size_t)lr * KT + ko;
    const __nv_bfloat16* bpL = Blo + (size_t)lr * KT + ko;
    const uint32_t dstb = smb + lr * 80 + ko * 2;

    float acc[2][8][4];
#pragma unroll
    for (int i = 0; i < 2; i++)
#pragma unroll
        for (int j = 0; j < 8; j++)
#pragma unroll
            for (int k = 0; k < 4; k++) acc[i][j][k] = 0.0f;

    constexpr int NCHUNK = KT / 32;

    {
        const uint32_t db = dstb;
        CP16(db + 0 * PLANE, apH);  CP16(db + 0 * PLANE + 16, apH + 8);
        CP16(db + 1 * PLANE, apL);  CP16(db + 1 * PLANE + 16, apL + 8);
        CP16(db + 2 * PLANE, bpH);  CP16(db + 2 * PLANE + 16, bpH + 8);
        CP16(db + 3 * PLANE, bpL);  CP16(db + 3 * PLANE + 16, bpL + 8);
        CPC();
    }

    int cur = 0;
#pragma unroll 1
    for (int c = 0; c < NCHUNK; c++) {
        if (c + 1 < NCHUNK) {
            const int kt = (c + 1) * 32;
            const uint32_t db = dstb + (cur ^ 1) * BUFB;
            CP16(db + 0 * PLANE, apH + kt);  CP16(db + 0 * PLANE + 16, apH + kt + 8);
            CP16(db + 1 * PLANE, apL + kt);  CP16(db + 1 * PLANE + 16, apL + kt + 8);
            CP16(db + 2 * PLANE, bpH + kt);  CP16(db + 2 * PLANE + 16, bpH + kt + 8);
            CP16(db + 3 * PLANE, bpL + kt);  CP16(db + 3 * PLANE + 16, bpL + kt + 8);
            CPC();
            CPW(1);
        } else {
            CPW(0);
        }
        __syncthreads();

        const unsigned short* sAhi = (const unsigned short*)(sm + (size_t)cur * BUFB + 0 * PLANE);
        const unsigned short* sAlo = (const unsigned short*)(sm + (size_t)cur * BUFB + 1 * PLANE);
        const unsigned short* sBhi = (const unsigned short*)(sm + (size_t)cur * BUFB + 2 * PLANE);
        const unsigned short* sBlo = (const unsigned short*)(sm + (size_t)cur * BUFB + 3 * PLANE);

#pragma unroll
        for (int ks = 0; ks < 2; ks++) {
            const int c0 = ks * 16 + 2 * tg;
            uint32_t ah[2][4], al[2][4];
#pragma unroll
            for (int mf = 0; mf < 2; mf++) {
                const int r0 = warp_m + mf * 16 + g;
                ah[mf][0] = *(const uint32_t*)&sAhi[(size_t)r0 * LDA + c0];
                ah[mf][1] = *(const uint32_t*)&sAhi[(size_t)(r0 + 8) * LDA + c0];
                ah[mf][2] = *(const uint32_t*)&sAhi[(size_t)r0 * LDA + c0 + 8];
                ah[mf][3] = *(const uint32_t*)&sAhi[(size_t)(r0 + 8) * LDA + c0 + 8];
                al[mf][0] = *(const uint32_t*)&sAlo[(size_t)r0 * LDA + c0];
                al[mf][1] = *(const uint32_t*)&sAlo[(size_t)(r0 + 8) * LDA + c0];
                al[mf][2] = *(const uint32_t*)&sAlo[(size_t)r0 * LDA + c0 + 8];
                al[mf][3] = *(const uint32_t*)&sAlo[(size_t)(r0 + 8) * LDA + c0 + 8];
            }
            uint32_t bh[8][2], bl[8][2];
#pragma unroll
            for (int nf = 0; nf < 8; nf++) {
                const int n = warp_n + nf * 8 + g;
                bh[nf][0] = *(const uint32_t*)&sBhi[(size_t)n * LDA + c0];
                bh[nf][1] = *(const uint32_t*)&sBhi[(size_t)n * LDA + c0 + 8];
                bl[nf][0] = *(const uint32_t*)&sBlo[(size_t)n * LDA + c0];
                bl[nf][1] = *(const uint32_t*)&sBlo[(size_t)n * LDA + c0 + 8];
            }
#pragma unroll
            for (int nf = 0; nf < 8; nf++) {
                MMA_BF16(acc[0][nf][0], acc[0][nf][1], acc[0][nf][2], acc[0][nf][3],
                         ah[0][0], ah[0][1], ah[0][2], ah[0][3], bh[nf][0], bh[nf][1]);
                MMA_BF16(acc[1][nf][0], acc[1][nf][1], acc[1][nf][2], acc[1][nf][3],
                         ah[1][0], ah[1][1], ah[1][2], ah[1][3], bh[nf][0], bh[nf][1]);
            }
#pragma unroll
            for (int nf = 0; nf < 8; nf++) {
                MMA_BF16(acc[0][nf][0], acc[0][nf][1], acc[0][nf][2], acc[0][nf][3],
                         ah[0][0], ah[0][1], ah[0][2], ah[0][3], bl[nf][0], bl[nf][1]);
                MMA_BF16(acc[1][nf][0], acc[1][nf][1], acc[1][nf][2], acc[1][nf][3],
                         ah[1][0], ah[1][1], ah[1][2], ah[1][3], bl[nf][0], bl[nf][1]);
            }
#pragma unroll
            for (int nf = 0; nf < 8; nf++) {
                MMA_BF16(acc[0][nf][0], acc[0][nf][1], acc[0][nf][2], acc[0][nf][3],
                         al[0][0], al[0][1], al[0][2], al[0][3], bh[nf][0], bh[nf][1]);
                MMA_BF16(acc[1][nf][0], acc[1][nf][1], acc[1][nf][2], acc[1][nf][3],
                         al[1][0], al[1][1], al[1][2], al[1][3], bh[nf][0], bh[nf][1]);
            }
        }
        __syncthreads();
        cur ^= 1;
    }

#pragma unroll
    for (int mf = 0; mf < 2; mf++) {
#pragma unroll
        for (int nf = 0; nf < 8; nf++) {
            const int row0 = blockRow + warp_m + mf * 16 + g;
            const int col = warp_n + nf * 8 + 2 * tg;
            if (row0 < M)
                *(float2*)(C + (size_t)row0 * 128 + col) =
                    make_float2(acc[mf][nf][0], acc[mf][nf][1]);
            if (row0 + 8 < M)
                *(float2*)(C + (size_t)(row0 + 8) * 128 + col) =
                    make_float2(acc[mf][nf][2], acc[mf][nf][3]);
        }
    }
}

// ---------------------------------------------------------------------------
// CSR propagation, 4-way MLP unroll; segments via g_off/g_end
// ---------------------------------------------------------------------------
#define PROP_BODY()                                                              \
    int e = g_off[warp];                                                         \
    const int end = g_end[warp];                                                 \
    for (; e + 4 <= end; e += 4) {                                               \
        int s0 = g_es[e], s1 = g_es[e + 1], s2 = g_es[e + 2], s3 = g_es[e + 3];  \
        float m0 = g_en[e], m1 = g_en[e + 1], m2 = g_en[e + 2], m3 = g_en[e + 3];\
        float4 v0 = ((const float4*)(H + (size_t)s0 * HID))[lane];               \
        float4 v1 = ((const float4*)(H + (size_t)s1 * HID))[lane];               \
        float4 v2 = ((const float4*)(H + (size_t)s2 * HID))[lane];               \
        float4 v3 = ((const float4*)(H + (size_t)s3 * HID))[lane];               \
        ax = fmaf(v0.x, m0, ax); ay = fmaf(v0.y, m0, ay);                        \
        az = fmaf(v0.z, m0, az); aw = fmaf(v0.w, m0, aw);                        \
        ax = fmaf(v1.x, m1, ax); ay = fmaf(v1.y, m1, ay);                        \
        az = fmaf(v1.z, m1, az); aw = fmaf(v1.w, m1, aw);                        \
        ax = fmaf(v2.x, m2, ax); ay = fmaf(v2.y, m2, ay);                        \
        az = fmaf(v2.z, m2, az); aw = fmaf(v2.w, m2, aw);                        \
        ax = fmaf(v3.x, m3, ax); ay = fmaf(v3.y, m3, ay);                        \
        az = fmaf(v3.z, m3, az); aw = fmaf(v3.w, m3, aw);                        \
    }                                                                            \
    for (; e < end; e++) {                                                       \
        int s0 = g_es[e];                                                        \
        float m0 = g_en[e];                                                      \
        float4 v0 = ((const float4*)(H + (size_t)s0 * HID))[lane];               \
        ax = fmaf(v0.x, m0, ax); ay = fmaf(v0.y, m0, ay);                        \
        az = fmaf(v0.z, m0, az); aw = fmaf(v0.w, m0, aw);                        \
    }

__global__ __launch_bounds__(256) void k_prop_csr_split(
    const float* __restrict__ H,
    const float* __restrict__ b)
{
    int warp = (blockIdx.x * blockDim.x + threadIdx.x) >> 5;
    if (warp >= NN) return;
    int lane = threadIdx.x & 31;

    float di = g_dinv[warp];
    float s = di * di;
    float4 bb = ((const float4*)b)[lane];
    float4 v = ((const float4*)(H + (size_t)warp * HID))[lane];
    float ax = fmaf(v.x, s, bb.x);
    float ay = fmaf(v.y, s, bb.y);
    float az = fmaf(v.z, s, bb.z);
    float aw = fmaf(v.w, s, bb.w);

    PROP_BODY()

    ax = fmaxf(ax, 0.f); ay = fmaxf(ay, 0.f);
    az = fmaxf(az, 0.f); aw = fmaxf(aw, 0.f);
    unsigned short h[4], l[4];
    split_bf16(ax, h[0], l[0]); split_bf16(ay, h[1], l[1]);
    split_bf16(az, h[2], l[2]); split_bf16(aw, h[3], l[3]);
    size_t o = (size_t)warp * HID + lane * 4;
    *(uint2*)(g_hhi + o) = make_uint2(h[0] | ((uint32_t)h[1] << 16), h[2] | ((uint32_t)h[3] << 16));
    *(uint2*)(g_hlo + o) = make_uint2(l[0] | ((uint32_t)l[1] << 16), l[2] | ((uint32_t)l[3] << 16));
}

__global__ __launch_bounds__(256) void k_prop_csr_out(
    const float* __restrict__ H,
    const float* __restrict__ bmu,
    const float* __restrict__ blv,
    float* __restrict__ out)
{
    int warp = (blockIdx.x * blockDim.x + threadIdx.x) >> 5;
    if (warp >= NN) return;
    int lane = threadIdx.x & 31;

    float di = g_dinv[warp];
    float s = di * di;
    float4 bb;
    float* dstp;
    if (lane < 16) {
        bb = ((const float4*)bmu)[lane];
        dstp = out + (size_t)warp * 64 + lane * 4;
    } else {
        bb = ((const float4*)blv)[lane - 16];
        dstp = out + (size_t)NN * 64 + (size_t)warp * 64 + (lane - 16) * 4;
    }
    float4 v = ((const float4*)(H + (size_t)warp * HID))[lane];
    float ax = fmaf(v.x, s, bb.x);
    float ay = fmaf(v.y, s, bb.y);
    float az = fmaf(v.z, s, bb.z);
    float aw = fmaf(v.w, s, bb.w);

    PROP_BODY()

    *(float4*)dstp = make_float4(ax, ay, az, aw);
}

// ---------------------------------------------------------------------------
extern "C" void kernel_launch(void* const* d_in, const int* in_sizes, int n_in,
                              void* d_out, int out_size)
{
    const float* x   = (const float*)d_in[0];
    const int*   ei  = (const int*)d_in[1];
    const float* W1  = (const float*)d_in[2];
    const float* b1  = (const float*)d_in[3];
    const float* Wmu = (const float*)d_in[4];
    const float* bmu = (const float*)d_in[5];
    const float* Wlv = (const float*)d_in[6];
    const float* blv = (const float*)d_in[7];
    float* out = (float*)d_out;

    const int* src = ei;
    const int* dst = ei + NE;

    float *h_ptr;
    cudaGetSymbolAddress((void**)&h_ptr, g_h);
    __nv_bfloat16 *hhi, *hlo, *w1hi, *w1lo, *w2hi, *w2lo;
    cudaGetSymbolAddress((void**)&hhi, g_hhi);
    cudaGetSymbolAddress((void**)&hlo, g_hlo);
    cudaGetSymbolAddress((void**)&w1hi, g_w1hi);
    cudaGetSymbolAddress((void**)&w1lo, g_w1lo);
    cudaGetSymbolAddress((void**)&w2hi, g_w2hi);
    cudaGetSymbolAddress((void**)&w2lo, g_w2lo);

    cudaFuncSetAttribute(tgemm_f32a, cudaFuncAttributeMaxDynamicSharedMemorySize, SMEM_F);
    cudaFuncSetAttribute(tgemm_bf16, cudaFuncAttributeMaxDynamicSharedMemorySize, SMEM_GEMM);

    const int TB = 256;

    // Side stream + fork/join events (created per call; not destroyed while
    // capture is live — host-side only, no device memory).
    cudaStream_t s2;
    cudaStreamCreateWithFlags(&s2, cudaStreamNonBlocking);
    cudaEvent_t ev_fork, ev_join;
    cudaEventCreateWithFlags(&ev_fork, cudaEventDisableTiming);
    cudaEventCreateWithFlags(&ev_join, cudaEventDisableTiming);

    // --- main stream: W1 conversion (GEMM1 dependency) ---
    k_convw1<<<128, TB>>>(W1);

    // --- fork: CSR build on s2, concurrent with GEMM1 on main ---
    cudaEventRecord(ev_fork, 0);
    cudaStreamWaitEvent(s2, ev_fork, 0);

    k_count_init<<<2564, TB, 0, s2>>>(dst, Wmu, Wlv);
    k_alloc<<<NB, 1024, 0, s2>>>();
    k_scatter<<<(NE + TB - 1) / TB, TB, 0, s2>>>(src, dst);
    cudaEventRecord(ev_join, s2);

    // --- main stream: Layer 1 GEMM ---
    tgemm_f32a<<<(NN + 127) / 128, 256, SMEM_F>>>(x, w1hi, w1lo, h_ptr, NN);

    // --- join: prop1 needs both GEMM1 and CSR ---
    cudaStreamWaitEvent(0, ev_join, 0);

    // --- Propagate + ReLU + split ---
    k_prop_csr_split<<<(NN * 32 + TB - 1) / TB, TB>>>(h_ptr, b1);

    // --- Layer 2: h2 = relu(p) @ [W_mu | W_logvar] ---
    tgemm_bf16<<<(NN + 127) / 128, 256, SMEM_GEMM>>>(hhi, hlo, w2hi, w2lo, h_ptr, NN);

    // --- Propagate to split output ---
    k_prop_csr_out<<<(NN * 32 + TB - 1) / TB, TB>>>(h_ptr, bmu, blv, out);
}